// round 1
// baseline (speedup 1.0000x reference)
#include <cuda_runtime.h>
#include <math.h>

#define NNODES 50000
#define HID 256
#define EMB 128
#define EMAX 800000
#define PB 120

// ---- scratch (static device globals: no allocation allowed) ----
__device__ float g_h[NNODES * HID];
__device__ float g_t1[NNODES * HID];
__device__ float g_g[NNODES * HID];
__device__ float g_acc[NNODES * HID];
__device__ float g_deg[NNODES];
__device__ float g_dinv[NNODES];
__device__ float g_psum[PB * HID];
__device__ float g_pmax[PB * HID];
__device__ float g_prob;
__device__ int g_src[EMAX];
__device__ int g_dst[EMAX];
__device__ int g_flag;

// ---------------- edge index dtype detection ----------------
// If edge_index is int64 little-endian with values < 50000, every odd int32
// word is 0. If it's int32 (JAX x64 disabled), odd words are real indices
// (nonzero with prob 1-1/50000 each).
__global__ void set_flag_k(int* flag) { *flag = 1; }

__global__ void detect_k(const int* p, int* flag) {
    int i = blockIdx.x * blockDim.x + threadIdx.x;  // 4096 checks
    if (p[2 * i + 1] != 0) *flag = 0;
}

__global__ void convert_edges_k(const void* ei, const int* flag, int* src, int* dst, int E) {
    int i = blockIdx.x * blockDim.x + threadIdx.x;
    if (i >= E) return;
    if (*flag) {
        const long long* p = (const long long*)ei;
        src[i] = (int)p[i];
        dst[i] = (int)p[E + i];
    } else {
        const int* p = (const int*)ei;
        src[i] = p[i];
        dst[i] = p[E + i];
    }
}

// ---------------- degree / normalization ----------------
__global__ void init_deg_k(float* deg) {
    int i = blockIdx.x * blockDim.x + threadIdx.x;
    if (i < NNODES) deg[i] = 1.0f;  // self loop
}

__global__ void deg_scatter_k(const int* dst, float* deg, int E) {
    int i = blockIdx.x * blockDim.x + threadIdx.x;
    if (i < E) atomicAdd(&deg[dst[i]], 1.0f);
}

__global__ void dinv_k(const float* deg, float* dinv) {
    int i = blockIdx.x * blockDim.x + threadIdx.x;
    if (i < NNODES) dinv[i] = rsqrtf(deg[i]);
}

// ---------------- GEMM: C[M,N] = A[M,K] @ B[K,N]  (+bias, relu, *dinv[row], dup-store) ----------------
// BM=BN=64, BK=16, 256 threads, 4x4 microtile per thread.
__global__ void gemm_k(const float* __restrict__ A, const float* __restrict__ B,
                       const float* __restrict__ bias, float* __restrict__ C,
                       float* __restrict__ C2, const float* __restrict__ dinvv,
                       int M, int K, int N, int do_relu) {
    __shared__ float As[16][64];
    __shared__ float Bs[16][64];
    int bm = blockIdx.x * 64;
    int bn = blockIdx.y * 64;
    int tid = threadIdx.x;
    int tx = tid & 15, ty = tid >> 4;

    float acc[4][4];
#pragma unroll
    for (int i = 0; i < 4; i++)
#pragma unroll
        for (int j = 0; j < 4; j++) acc[i][j] = 0.0f;

    int am = tid >> 2, ak = (tid & 3) << 2;   // A loader: row am, 4 k's
    int bk = tid >> 4, bnn = (tid & 15) << 2; // B loader: row bk, 4 n's

    for (int k0 = 0; k0 < K; k0 += 16) {
        float4 av;
        if (bm + am < M)
            av = *(const float4*)(A + (size_t)(bm + am) * K + k0 + ak);
        else
            av = make_float4(0.f, 0.f, 0.f, 0.f);
        As[ak + 0][am] = av.x;
        As[ak + 1][am] = av.y;
        As[ak + 2][am] = av.z;
        As[ak + 3][am] = av.w;

        float4 bv = *(const float4*)(B + (size_t)(k0 + bk) * N + bn + bnn);
        *(float4*)&Bs[bk][bnn] = bv;
        __syncthreads();

#pragma unroll
        for (int kk = 0; kk < 16; kk++) {
            float4 a = *(const float4*)&As[kk][ty << 2];
            float4 b = *(const float4*)&Bs[kk][tx << 2];
            acc[0][0] += a.x * b.x; acc[0][1] += a.x * b.y; acc[0][2] += a.x * b.z; acc[0][3] += a.x * b.w;
            acc[1][0] += a.y * b.x; acc[1][1] += a.y * b.y; acc[1][2] += a.y * b.z; acc[1][3] += a.y * b.w;
            acc[2][0] += a.z * b.x; acc[2][1] += a.z * b.y; acc[2][2] += a.z * b.z; acc[2][3] += a.z * b.w;
            acc[3][0] += a.w * b.x; acc[3][1] += a.w * b.y; acc[3][2] += a.w * b.z; acc[3][3] += a.w * b.w;
        }
        __syncthreads();
    }

#pragma unroll
    for (int i = 0; i < 4; i++) {
        int m = bm + (ty << 2) + i;
        if (m >= M) continue;
        float scale = dinvv ? dinvv[m] : 1.0f;
        float4 o;
        float* op = &o.x;
#pragma unroll
        for (int j = 0; j < 4; j++) {
            int n = bn + (tx << 2) + j;
            float v = acc[i][j];
            if (bias) v += bias[n];
            if (do_relu) v = fmaxf(v, 0.0f);
            op[j] = v * scale;
        }
        size_t off = (size_t)m * N + bn + (tx << 2);
        *(float4*)(C + off) = o;
        if (C2) *(float4*)(C2 + off) = o;
    }
}

// ---------------- edge scatter: acc[dst] += g[src]  (float4 granularity) ----------------
__global__ void scatter_k(const int* __restrict__ src, const int* __restrict__ dst,
                          const float* __restrict__ g, float* __restrict__ acc, int E) {
    long long t = (long long)blockIdx.x * blockDim.x + threadIdx.x;
    long long total = (long long)E * 64;
    if (t >= total) return;
    int e = (int)(t >> 6);
    int c = (int)(t & 63);
    int s = src[e], d = dst[e];
    float4 v = *(const float4*)(g + (size_t)s * HID + c * 4);
    float* p = acc + (size_t)d * HID + c * 4;
    atomicAdd(p + 0, v.x);
    atomicAdd(p + 1, v.y);
    atomicAdd(p + 2, v.z);
    atomicAdd(p + 3, v.w);
}

// ---------------- finalize: h = relu(dinv[m]*acc + bias) ----------------
__global__ void finalize_k(const float* __restrict__ acc, const float* __restrict__ dinvv,
                           const float* __restrict__ bias, float* __restrict__ h) {
    int idx = blockIdx.x * blockDim.x + threadIdx.x;  // over NNODES*64 float4s
    if (idx >= NNODES * 64) return;
    int m = idx >> 6;
    int c = (idx & 63) << 2;
    float dv = dinvv[m];
    float4 a = *(const float4*)(acc + (size_t)idx * 4);
    float4 o;
    o.x = fmaxf(a.x * dv + bias[c + 0], 0.0f);
    o.y = fmaxf(a.y * dv + bias[c + 1], 0.0f);
    o.z = fmaxf(a.z * dv + bias[c + 2], 0.0f);
    o.w = fmaxf(a.w * dv + bias[c + 3], 0.0f);
    *(float4*)(h + (size_t)idx * 4) = o;
}

// ---------------- pooling partials: per-block row-stripe sum/max per column ----------------
__global__ void pool_partial_k(const float* __restrict__ h, float* __restrict__ psum,
                               float* __restrict__ pmax) {
    int col = threadIdx.x;  // 256
    int b = blockIdx.x;     // PB
    float s = 0.0f, m = -1e30f;
    for (int r = b; r < NNODES; r += PB) {
        float v = h[(size_t)r * HID + col];
        s += v;
        m = fmaxf(m, v);
    }
    psum[b * HID + col] = s;
    pmax[b * HID + col] = m;
}

// ---------------- head: pool combine + MLPs + scalar edge prob ----------------
__global__ void head_k(const float* __restrict__ psum, const float* __restrict__ pmax,
                       const float* __restrict__ Wg1, const float* __restrict__ bg1,
                       const float* __restrict__ Wg2, const float* __restrict__ bg2,
                       const float* __restrict__ Wd1, const float* __restrict__ bd1,
                       const float* __restrict__ Wd2, const float* __restrict__ bd2,
                       float* __restrict__ out, float* __restrict__ prob) {
    __shared__ float rep[2 * HID];
    __shared__ float u1[HID];
    __shared__ float ge[EMB];
    __shared__ float v1[HID];
    __shared__ float vv[HID];
    __shared__ float red[HID];
    int t = threadIdx.x;  // 512

    if (t < HID) {
        float s = 0.0f;
        for (int i = 0; i < PB; i++) s += psum[i * HID + t];
        rep[t] = s * (1.0f / NNODES);
    } else {
        int c = t - HID;
        float m = -1e30f;
        for (int i = 0; i < PB; i++) m = fmaxf(m, pmax[i * HID + c]);
        rep[HID + c] = m;
    }
    __syncthreads();

    if (t < HID) {
        float s = bg1[t];
        for (int k = 0; k < 2 * HID; k++) s += rep[k] * Wg1[k * HID + t];
        u1[t] = fmaxf(s, 0.0f);
    }
    __syncthreads();

    if (t < EMB) {
        float s = bg2[t];
        for (int k = 0; k < HID; k++) s += u1[k] * Wg2[k * EMB + t];
        ge[t] = s;
        out[t] = s;  // graph_embedding -> d_out[0:128]
    }
    __syncthreads();

    if (t < HID) {
        float s = bd1[t];
        for (int k = 0; k < EMB; k++) s += ge[k] * Wd1[k * HID + t];
        v1[t] = fmaxf(s, 0.0f);
    }
    __syncthreads();

    if (t < HID) {
        float s = bd2[t];
        for (int k = 0; k < HID; k++) s += v1[k] * Wd2[k * HID + t];
        vv[t] = s;
    }
    __syncthreads();

    if (t < HID) red[t] = vv[t] * vv[t];
    __syncthreads();
    for (int s = HID / 2; s > 0; s >>= 1) {
        if (t < s) red[t] += red[t + s];
        __syncthreads();
    }
    if (t == 0) *prob = 1.0f / (1.0f + expf(-red[0]));
}

__global__ void fill_probs_k(float* __restrict__ out, const float* __restrict__ prob, int E) {
    int i = blockIdx.x * blockDim.x + threadIdx.x;
    if (i < E) out[EMB + i] = *prob;
}

// ---------------- launch ----------------
extern "C" void kernel_launch(void* const* d_in, const int* in_sizes, int n_in,
                              void* d_out, int out_size) {
    const float* x = (const float*)d_in[0];
    const void* ei = d_in[1];
    const float* W1 = (const float*)d_in[2];
    const float* b1 = (const float*)d_in[3];
    const float* W2 = (const float*)d_in[4];
    const float* b2 = (const float*)d_in[5];
    const float* convW = (const float*)d_in[6];
    const float* convb = (const float*)d_in[7];
    const float* Wg1 = (const float*)d_in[8];
    const float* bg1 = (const float*)d_in[9];
    const float* Wg2 = (const float*)d_in[10];
    const float* bg2 = (const float*)d_in[11];
    const float* Wd1 = (const float*)d_in[12];
    const float* bd1 = (const float*)d_in[13];
    const float* Wd2 = (const float*)d_in[14];
    const float* bd2 = (const float*)d_in[15];

    int E = in_sizes[1] / 2;

    float *h, *t1, *g, *acc, *deg, *dinv, *psum, *pmax, *prob;
    int *src, *dst, *flag;
    cudaGetSymbolAddress((void**)&h, g_h);
    cudaGetSymbolAddress((void**)&t1, g_t1);
    cudaGetSymbolAddress((void**)&g, g_g);
    cudaGetSymbolAddress((void**)&acc, g_acc);
    cudaGetSymbolAddress((void**)&deg, g_deg);
    cudaGetSymbolAddress((void**)&dinv, g_dinv);
    cudaGetSymbolAddress((void**)&psum, g_psum);
    cudaGetSymbolAddress((void**)&pmax, g_pmax);
    cudaGetSymbolAddress((void**)&prob, g_prob);
    cudaGetSymbolAddress((void**)&src, g_src);
    cudaGetSymbolAddress((void**)&dst, g_dst);
    cudaGetSymbolAddress((void**)&flag, g_flag);

    // dtype sniff + edge conversion to int32
    set_flag_k<<<1, 1>>>(flag);
    detect_k<<<16, 256>>>((const int*)ei, flag);
    convert_edges_k<<<(E + 255) / 256, 256>>>(ei, flag, src, dst, E);

    // degrees + dinv
    init_deg_k<<<(NNODES + 255) / 256, 256>>>(deg);
    deg_scatter_k<<<(E + 255) / 256, 256>>>(dst, deg, E);
    dinv_k<<<(NNODES + 255) / 256, 256>>>(deg, dinv);

    // node encoder
    dim3 ggrid((NNODES + 63) / 64, HID / 64);
    gemm_k<<<ggrid, 256>>>(x, W1, b1, t1, nullptr, nullptr, NNODES, 64, HID, 1);
    gemm_k<<<ggrid, 256>>>(t1, W2, b2, h, nullptr, nullptr, NNODES, HID, HID, 0);

    // GCN layers: g = dinv*(h@W) (also initializes acc with self-loop term),
    // scatter edges, finalize h = relu(dinv*acc + b)
    long long sc_total = (long long)E * 64;
    int sc_blocks = (int)((sc_total + 255) / 256);
    for (int l = 0; l < 3; l++) {
        gemm_k<<<ggrid, 256>>>(h, convW + (size_t)l * HID * HID, nullptr, g, acc, dinv,
                               NNODES, HID, HID, 0);
        scatter_k<<<sc_blocks, 256>>>(src, dst, g, acc, E);
        finalize_k<<<(NNODES * 64 + 255) / 256, 256>>>(acc, dinv, convb + (size_t)l * HID, h);
    }

    // pooling + heads + output
    pool_partial_k<<<PB, 256>>>(h, psum, pmax);
    head_k<<<1, 512>>>(psum, pmax, Wg1, bg1, Wg2, bg2, Wd1, bd1, Wd2, bd2, (float*)d_out, prob);
    fill_probs_k<<<(E + 255) / 256, 256>>>((float*)d_out, prob, E);
}

// round 3
// speedup vs baseline: 3.9747x; 3.9747x over previous
#include <cuda_runtime.h>
#include <math.h>
#include <stdint.h>

#define NNODES 50000
#define HID 256
#define EMB 128
#define EMAX 800000
#define PB 120
#define NB_M 391   // ceil(50000/128)
#define SCAN_B 196 // ceil(50000/256)

// ---- scratch (static device globals: no allocation allowed) ----
__device__ float g_h[NNODES * HID];
__device__ float g_t1[NNODES * HID];
__device__ float g_g[NNODES * HID];
__device__ float g_dinv[NNODES];
__device__ float g_psum[PB * HID];
__device__ float g_pmax[PB * HID];
__device__ float g_prob;
__device__ int g_src[EMAX];
__device__ int g_dst[EMAX];
__device__ int g_cnt[NNODES];
__device__ int g_cursor[NNODES];
__device__ int g_off[NNODES + 1];
__device__ int g_adj[EMAX];
__device__ int g_bsum[SCAN_B];
__device__ int g_flag;

// ---------------- edge index dtype detection ----------------
__global__ void set_flag_k(int* flag) { *flag = 1; }

__global__ void detect_k(const int* p, int* flag) {
    int i = blockIdx.x * blockDim.x + threadIdx.x;  // 4096 checks
    if (p[2 * i + 1] != 0) *flag = 0;
}

__global__ void convert_edges_k(const void* ei, const int* flag, int* src, int* dst, int E) {
    int i = blockIdx.x * blockDim.x + threadIdx.x;
    if (i >= E) return;
    if (*flag) {
        const long long* p = (const long long*)ei;
        src[i] = (int)p[i];
        dst[i] = (int)p[E + i];
    } else {
        const int* p = (const int*)ei;
        src[i] = p[i];
        dst[i] = p[E + i];
    }
}

// ---------------- CSR build ----------------
__global__ void count_k(const int* __restrict__ dst, int* __restrict__ cnt, int E) {
    int i = blockIdx.x * blockDim.x + threadIdx.x;
    if (i < E) atomicAdd(&cnt[dst[i]], 1);
}

__global__ void dinv_k(const int* __restrict__ cnt, float* __restrict__ dinv) {
    int i = blockIdx.x * blockDim.x + threadIdx.x;
    if (i < NNODES) dinv[i] = rsqrtf((float)cnt[i] + 1.0f);
}

__global__ void scan1_k(const int* __restrict__ cnt, int* __restrict__ bsum) {
    __shared__ int s[256];
    int t = threadIdx.x;
    int i = blockIdx.x * 256 + t;
    s[t] = (i < NNODES) ? cnt[i] : 0;
    __syncthreads();
    for (int d = 128; d > 0; d >>= 1) {
        if (t < d) s[t] += s[t + d];
        __syncthreads();
    }
    if (t == 0) bsum[blockIdx.x] = s[0];
}

__global__ void scan2_k(int* bsum) {
    if (threadIdx.x == 0) {
        int run = 0;
        for (int b = 0; b < SCAN_B; b++) {
            int v = bsum[b];
            bsum[b] = run;
            run += v;
        }
    }
}

__global__ void scan3_k(const int* __restrict__ cnt, const int* __restrict__ bsum,
                        int* __restrict__ off) {
    __shared__ int s[256];
    int t = threadIdx.x;
    int i = blockIdx.x * 256 + t;
    int val = (i < NNODES) ? cnt[i] : 0;
    s[t] = val;
    __syncthreads();
    for (int d = 1; d < 256; d <<= 1) {
        int tmp = (t >= d) ? s[t - d] : 0;
        __syncthreads();
        s[t] += tmp;
        __syncthreads();
    }
    if (i <= NNODES) off[i] = bsum[blockIdx.x] + s[t] - val;
}

__global__ void fill_k(const int* __restrict__ src, const int* __restrict__ dst,
                       const int* __restrict__ off, int* __restrict__ cursor,
                       int* __restrict__ adj, int E) {
    int i = blockIdx.x * blockDim.x + threadIdx.x;
    if (i >= E) return;
    int d = dst[i];
    int p = atomicAdd(&cursor[d], 1);
    adj[off[d] + p] = src[i];
}

// ---------------- TF32 tensor-core GEMM ----------------
// C[M,256] = A[M,K] @ B[K,256]  (+bias, relu, *dinv[row])
// Block tile 128x256xBK32, 8 warps of 64x64, mma.m16n8k8.tf32.
#define AS_STRIDE 36
#define BS_STRIDE 264
#define GEMM_SMEM ((128 * AS_STRIDE + 32 * BS_STRIDE) * 4)

__device__ __forceinline__ float tf32r(float x) {
    uint32_t u;
    asm("cvt.rna.tf32.f32 %0, %1;" : "=r"(u) : "f"(x));
    return __uint_as_float(u);
}

__global__ __launch_bounds__(256, 1) void gemm_tf32_k(
    const float* __restrict__ A, const float* __restrict__ B,
    const float* __restrict__ bias, float* __restrict__ C,
    const float* __restrict__ dinvv, int M, int K, int relu_flag) {
    extern __shared__ float sm[];
    float* As = sm;                    // [128][36]
    float* Bs = sm + 128 * AS_STRIDE;  // [32][264]

    int tid = threadIdx.x;
    int warp = tid >> 5;
    int lane = tid & 31;
    int grp = lane >> 2;   // 0..7
    int tig = lane & 3;    // 0..3
    int wm = warp >> 2;    // 0..1 -> m offset wm*64
    int wn = warp & 3;     // 0..3 -> n offset wn*64
    int bm = blockIdx.x * 128;

    float c[4][8][4];
#pragma unroll
    for (int mt = 0; mt < 4; mt++)
#pragma unroll
        for (int nt = 0; nt < 8; nt++)
#pragma unroll
            for (int q = 0; q < 4; q++) c[mt][nt][q] = 0.0f;

    for (int k0 = 0; k0 < K; k0 += 32) {
        // stage A tile: 128 rows x 32 cols
#pragma unroll
        for (int i = 0; i < 4; i++) {
            int idx = tid + i * 256;
            int row = idx >> 3;
            int c4 = (idx & 7) << 2;
            int gm = bm + row;
            float4 v = make_float4(0.f, 0.f, 0.f, 0.f);
            if (gm < M) v = *(const float4*)(A + (size_t)gm * K + k0 + c4);
            float4 w = make_float4(tf32r(v.x), tf32r(v.y), tf32r(v.z), tf32r(v.w));
            *(float4*)(As + row * AS_STRIDE + c4) = w;
        }
        // stage B tile: 32 rows x 256 cols
#pragma unroll
        for (int i = 0; i < 8; i++) {
            int idx = tid + i * 256;
            int row = idx >> 6;
            int c4 = (idx & 63) << 2;
            float4 v = *(const float4*)(B + (size_t)(k0 + row) * 256 + c4);
            float4 w = make_float4(tf32r(v.x), tf32r(v.y), tf32r(v.z), tf32r(v.w));
            *(float4*)(Bs + row * BS_STRIDE + c4) = w;
        }
        __syncthreads();

#pragma unroll
        for (int ks = 0; ks < 4; ks++) {
            int kk = ks << 3;
            uint32_t af[4][4];
#pragma unroll
            for (int mt = 0; mt < 4; mt++) {
                int r0 = wm * 64 + mt * 16 + grp;
                af[mt][0] = __float_as_uint(As[r0 * AS_STRIDE + kk + tig]);
                af[mt][1] = __float_as_uint(As[(r0 + 8) * AS_STRIDE + kk + tig]);
                af[mt][2] = __float_as_uint(As[r0 * AS_STRIDE + kk + tig + 4]);
                af[mt][3] = __float_as_uint(As[(r0 + 8) * AS_STRIDE + kk + tig + 4]);
            }
#pragma unroll
            for (int nt = 0; nt < 8; nt++) {
                int col = wn * 64 + nt * 8 + grp;
                uint32_t b0 = __float_as_uint(Bs[(kk + tig) * BS_STRIDE + col]);
                uint32_t b1 = __float_as_uint(Bs[(kk + tig + 4) * BS_STRIDE + col]);
#pragma unroll
                for (int mt = 0; mt < 4; mt++) {
                    asm volatile(
                        "mma.sync.aligned.m16n8k8.row.col.f32.tf32.tf32.f32 "
                        "{%0,%1,%2,%3},{%4,%5,%6,%7},{%8,%9},{%0,%1,%2,%3};\n"
                        : "+f"(c[mt][nt][0]), "+f"(c[mt][nt][1]),
                          "+f"(c[mt][nt][2]), "+f"(c[mt][nt][3])
                        : "r"(af[mt][0]), "r"(af[mt][1]), "r"(af[mt][2]), "r"(af[mt][3]),
                          "r"(b0), "r"(b1));
                }
            }
        }
        __syncthreads();
    }

    // epilogue
#pragma unroll
    for (int mt = 0; mt < 4; mt++) {
        int r0 = bm + wm * 64 + mt * 16 + grp;
        int r1 = r0 + 8;
        float d0 = 1.0f, d1 = 1.0f;
        if (dinvv) {
            if (r0 < M) d0 = dinvv[r0];
            if (r1 < M) d1 = dinvv[r1];
        }
#pragma unroll
        for (int nt = 0; nt < 8; nt++) {
            int col = wn * 64 + nt * 8 + 2 * tig;
            float b0f = 0.f, b1f = 0.f;
            if (bias) { b0f = bias[col]; b1f = bias[col + 1]; }
            float v0 = c[mt][nt][0] + b0f;
            float v1 = c[mt][nt][1] + b1f;
            float v2 = c[mt][nt][2] + b0f;
            float v3 = c[mt][nt][3] + b1f;
            if (relu_flag) {
                v0 = fmaxf(v0, 0.f); v1 = fmaxf(v1, 0.f);
                v2 = fmaxf(v2, 0.f); v3 = fmaxf(v3, 0.f);
            }
            v0 *= d0; v1 *= d0; v2 *= d1; v3 *= d1;
            if (r0 < M) *(float2*)(C + (size_t)r0 * 256 + col) = make_float2(v0, v1);
            if (r1 < M) *(float2*)(C + (size_t)r1 * 256 + col) = make_float2(v2, v3);
        }
    }
}

// ---------------- CSR aggregate + finalize fused ----------------
// h[d] = relu(dinv[d] * (g[d] + sum_{s in adj[d]} g[s]) + bias)
__global__ void aggregate_k(const int* __restrict__ off, const int* __restrict__ adj,
                            const float* __restrict__ g, const float* __restrict__ dinv,
                            const float* __restrict__ bias, float* __restrict__ h) {
    int gw = (blockIdx.x * blockDim.x + threadIdx.x) >> 5;
    if (gw >= NNODES * 2) return;
    int node = gw >> 1;
    int lane = threadIdx.x & 31;
    int col = ((gw & 1) << 7) + (lane << 2);

    float4 acc = *(const float4*)(g + (size_t)node * HID + col);  // self loop
    int e0 = off[node], e1 = off[node + 1];
    for (int j = e0; j < e1; j++) {
        int s = adj[j];
        float4 v = *(const float4*)(g + (size_t)s * HID + col);
        acc.x += v.x; acc.y += v.y; acc.z += v.z; acc.w += v.w;
    }
    float dv = dinv[node];
    float4 o;
    o.x = fmaxf(fmaf(acc.x, dv, bias[col + 0]), 0.f);
    o.y = fmaxf(fmaf(acc.y, dv, bias[col + 1]), 0.f);
    o.z = fmaxf(fmaf(acc.z, dv, bias[col + 2]), 0.f);
    o.w = fmaxf(fmaf(acc.w, dv, bias[col + 3]), 0.f);
    *(float4*)(h + (size_t)node * HID + col) = o;
}

// ---------------- pooling partials ----------------
__global__ void pool_partial_k(const float* __restrict__ h, float* __restrict__ psum,
                               float* __restrict__ pmax) {
    int col = threadIdx.x;  // 256
    int b = blockIdx.x;     // PB
    float s = 0.0f, m = -1e30f;
    for (int r = b; r < NNODES; r += PB) {
        float v = h[(size_t)r * HID + col];
        s += v;
        m = fmaxf(m, v);
    }
    psum[b * HID + col] = s;
    pmax[b * HID + col] = m;
}

// ---------------- head ----------------
__global__ void head_k(const float* __restrict__ psum, const float* __restrict__ pmax,
                       const float* __restrict__ Wg1, const float* __restrict__ bg1,
                       const float* __restrict__ Wg2, const float* __restrict__ bg2,
                       const float* __restrict__ Wd1, const float* __restrict__ bd1,
                       const float* __restrict__ Wd2, const float* __restrict__ bd2,
                       float* __restrict__ out, float* __restrict__ prob) {
    __shared__ float rep[2 * HID];
    __shared__ float u1[HID];
    __shared__ float ge[EMB];
    __shared__ float v1[HID];
    __shared__ float vv[HID];
    __shared__ float red[HID];
    int t = threadIdx.x;  // 512

    if (t < HID) {
        float s = 0.0f;
        for (int i = 0; i < PB; i++) s += psum[i * HID + t];
        rep[t] = s * (1.0f / NNODES);
    } else {
        int c = t - HID;
        float m = -1e30f;
        for (int i = 0; i < PB; i++) m = fmaxf(m, pmax[i * HID + c]);
        rep[HID + c] = m;
    }
    __syncthreads();

    if (t < HID) {
        float s = bg1[t];
        for (int k = 0; k < 2 * HID; k++) s += rep[k] * Wg1[k * HID + t];
        u1[t] = fmaxf(s, 0.0f);
    }
    __syncthreads();

    if (t < EMB) {
        float s = bg2[t];
        for (int k = 0; k < HID; k++) s += u1[k] * Wg2[k * EMB + t];
        ge[t] = s;
        out[t] = s;
    }
    __syncthreads();

    if (t < HID) {
        float s = bd1[t];
        for (int k = 0; k < EMB; k++) s += ge[k] * Wd1[k * HID + t];
        v1[t] = fmaxf(s, 0.0f);
    }
    __syncthreads();

    if (t < HID) {
        float s = bd2[t];
        for (int k = 0; k < HID; k++) s += v1[k] * Wd2[k * HID + t];
        vv[t] = s;
    }
    __syncthreads();

    if (t < HID) red[t] = vv[t] * vv[t];
    __syncthreads();
    for (int s = HID / 2; s > 0; s >>= 1) {
        if (t < s) red[t] += red[t + s];
        __syncthreads();
    }
    if (t == 0) *prob = 1.0f / (1.0f + expf(-red[0]));
}

__global__ void fill_probs_k(float* __restrict__ out, const float* __restrict__ prob, int E) {
    int i = blockIdx.x * blockDim.x + threadIdx.x;
    if (i < E) out[EMB + i] = *prob;
}

// ---------------- launch ----------------
extern "C" void kernel_launch(void* const* d_in, const int* in_sizes, int n_in,
                              void* d_out, int out_size) {
    const float* x = (const float*)d_in[0];
    const void* ei = d_in[1];
    const float* W1 = (const float*)d_in[2];
    const float* b1 = (const float*)d_in[3];
    const float* W2 = (const float*)d_in[4];
    const float* b2 = (const float*)d_in[5];
    const float* convW = (const float*)d_in[6];
    const float* convb = (const float*)d_in[7];
    const float* Wg1 = (const float*)d_in[8];
    const float* bg1 = (const float*)d_in[9];
    const float* Wg2 = (const float*)d_in[10];
    const float* bg2 = (const float*)d_in[11];
    const float* Wd1 = (const float*)d_in[12];
    const float* bd1 = (const float*)d_in[13];
    const float* Wd2 = (const float*)d_in[14];
    const float* bd2 = (const float*)d_in[15];

    int E = in_sizes[1] / 2;

    float *h, *t1, *g, *dinv, *psum, *pmax, *prob;
    int *src, *dst, *cnt, *cursor, *off, *adj, *bsum, *flag;
    cudaGetSymbolAddress((void**)&h, g_h);
    cudaGetSymbolAddress((void**)&t1, g_t1);
    cudaGetSymbolAddress((void**)&g, g_g);
    cudaGetSymbolAddress((void**)&dinv, g_dinv);
    cudaGetSymbolAddress((void**)&psum, g_psum);
    cudaGetSymbolAddress((void**)&pmax, g_pmax);
    cudaGetSymbolAddress((void**)&prob, g_prob);
    cudaGetSymbolAddress((void**)&src, g_src);
    cudaGetSymbolAddress((void**)&dst, g_dst);
    cudaGetSymbolAddress((void**)&cnt, g_cnt);
    cudaGetSymbolAddress((void**)&cursor, g_cursor);
    cudaGetSymbolAddress((void**)&off, g_off);
    cudaGetSymbolAddress((void**)&adj, g_adj);
    cudaGetSymbolAddress((void**)&bsum, g_bsum);
    cudaGetSymbolAddress((void**)&flag, g_flag);

    // no static guard — must be deterministic & safe on every call
    cudaFuncSetAttribute(gemm_tf32_k, cudaFuncAttributeMaxDynamicSharedMemorySize, GEMM_SMEM);

    // dtype sniff + edge conversion
    set_flag_k<<<1, 1>>>(flag);
    detect_k<<<16, 256>>>((const int*)ei, flag);
    convert_edges_k<<<(E + 255) / 256, 256>>>(ei, flag, src, dst, E);

    // CSR build + dinv
    cudaMemsetAsync(cnt, 0, NNODES * sizeof(int));
    cudaMemsetAsync(cursor, 0, NNODES * sizeof(int));
    count_k<<<(E + 255) / 256, 256>>>(dst, cnt, E);
    dinv_k<<<(NNODES + 255) / 256, 256>>>(cnt, dinv);
    scan1_k<<<SCAN_B, 256>>>(cnt, bsum);
    scan2_k<<<1, 32>>>(bsum);
    scan3_k<<<SCAN_B, 256>>>(cnt, bsum, off);
    fill_k<<<(E + 255) / 256, 256>>>(src, dst, off, cursor, adj, E);

    // node encoder (tf32 tensor-core GEMMs)
    gemm_tf32_k<<<NB_M, 256, GEMM_SMEM>>>(x, W1, b1, t1, nullptr, NNODES, 64, 1);
    gemm_tf32_k<<<NB_M, 256, GEMM_SMEM>>>(t1, W2, b2, h, nullptr, NNODES, HID, 0);

    // GCN layers
    int agg_blocks = (NNODES * 2 * 32 + 255) / 256;
    for (int l = 0; l < 3; l++) {
        gemm_tf32_k<<<NB_M, 256, GEMM_SMEM>>>(h, convW + (size_t)l * HID * HID, nullptr, g,
                                              dinv, NNODES, HID, 0);
        aggregate_k<<<agg_blocks, 256>>>(off, adj, g, dinv, convb + (size_t)l * HID, h);
    }

    // pooling + heads + output
    pool_partial_k<<<PB, 256>>>(h, psum, pmax);
    head_k<<<1, 512>>>(psum, pmax, Wg1, bg1, Wg2, bg2, Wd1, bd1, Wd2, bd2, (float*)d_out, prob);
    fill_probs_k<<<(E + 255) / 256, 256>>>((float*)d_out, prob, E);
}

// round 4
// speedup vs baseline: 4.3259x; 1.0884x over previous
#include <cuda_runtime.h>
#include <math.h>
#include <stdint.h>

#define NNODES 50000
#define HID 256
#define EMB 128
#define EMAX 800000
#define PB 120
#define NB_M 391   // ceil(50000/128)
#define SCAN_B 196 // ceil(50000/256)

// ---- scratch (static device globals: no allocation allowed) ----
__device__ float g_h[NNODES * HID];
__device__ float g_t1[NNODES * HID];
__device__ float g_g[NNODES * HID];
__device__ float g_dinv[NNODES];
__device__ float g_psum[PB * HID];
__device__ float g_pmax[PB * HID];
__device__ float g_prob;
__device__ int g_src[EMAX];
__device__ int g_dst[EMAX];
__device__ int g_cnt[NNODES];
__device__ int g_cursor[NNODES];
__device__ int g_off[NNODES + 1];
__device__ int g_adj[EMAX];
__device__ int g_bsum[SCAN_B];
__device__ int g_flag;

// ---------------- small utility kernels ----------------
__global__ void set_flag_k(int* flag) { *flag = 1; }

__global__ void zero2_k(int* a, int* b, int n) {
    int i = blockIdx.x * blockDim.x + threadIdx.x;
    if (i < n) { a[i] = 0; b[i] = 0; }
}

// int64-vs-int32 sniff: int64 LE indices < 50000 have all odd words zero
__global__ void detect_k(const int* p, int* flag) {
    int i = blockIdx.x * blockDim.x + threadIdx.x;  // 4096 checks
    if (p[2 * i + 1] != 0) *flag = 0;
}

// convert + degree count fused
__global__ void convert_edges_k(const void* ei, const int* flag, int* src, int* dst,
                                int* cnt, int E) {
    int i = blockIdx.x * blockDim.x + threadIdx.x;
    if (i >= E) return;
    int s, d;
    if (*flag) {
        const long long* p = (const long long*)ei;
        s = (int)p[i];
        d = (int)p[E + i];
    } else {
        const int* p = (const int*)ei;
        s = p[i];
        d = p[E + i];
    }
    src[i] = s;
    dst[i] = d;
    atomicAdd(&cnt[d], 1);
}

__global__ void dinv_k(const int* __restrict__ cnt, float* __restrict__ dinv) {
    int i = blockIdx.x * blockDim.x + threadIdx.x;
    if (i < NNODES) dinv[i] = rsqrtf((float)cnt[i] + 1.0f);
}

// ---------------- CSR scan + fill ----------------
__global__ void scan1_k(const int* __restrict__ cnt, int* __restrict__ bsum) {
    __shared__ int s[256];
    int t = threadIdx.x;
    int i = blockIdx.x * 256 + t;
    s[t] = (i < NNODES) ? cnt[i] : 0;
    __syncthreads();
    for (int d = 128; d > 0; d >>= 1) {
        if (t < d) s[t] += s[t + d];
        __syncthreads();
    }
    if (t == 0) bsum[blockIdx.x] = s[0];
}

__global__ void scan2_k(int* bsum) {
    if (threadIdx.x == 0) {
        int run = 0;
        for (int b = 0; b < SCAN_B; b++) {
            int v = bsum[b];
            bsum[b] = run;
            run += v;
        }
    }
}

__global__ void scan3_k(const int* __restrict__ cnt, const int* __restrict__ bsum,
                        int* __restrict__ off) {
    __shared__ int s[256];
    int t = threadIdx.x;
    int i = blockIdx.x * 256 + t;
    int val = (i < NNODES) ? cnt[i] : 0;
    s[t] = val;
    __syncthreads();
    for (int d = 1; d < 256; d <<= 1) {
        int tmp = (t >= d) ? s[t - d] : 0;
        __syncthreads();
        s[t] += tmp;
        __syncthreads();
    }
    if (i <= NNODES) off[i] = bsum[blockIdx.x] + s[t] - val;
}

__global__ void fill_k(const int* __restrict__ src, const int* __restrict__ dst,
                       const int* __restrict__ off, int* __restrict__ cursor,
                       int* __restrict__ adj, int E) {
    int i = blockIdx.x * blockDim.x + threadIdx.x;
    if (i >= E) return;
    int d = dst[i];
    int p = atomicAdd(&cursor[d], 1);
    adj[off[d] + p] = src[i];
}

// ---------------- TF32 tensor-core GEMM, cp.async double-buffered ----------------
// C[M,256] = A[M,K] @ B[K,256]  (+bias, relu, *dinv[row])
// Block tile 128x256x32, 8 warps of 64x64, mma.m16n8k8.tf32, 2-stage pipeline.
#define AS_STRIDE 36
#define BS_STRIDE 264
#define STAGE_FLOATS (128 * AS_STRIDE + 32 * BS_STRIDE)
#define GEMM_SMEM (2 * STAGE_FLOATS * 4)

__device__ __forceinline__ uint32_t tf32bits(float x) {
    uint32_t u;
    asm("cvt.rna.tf32.f32 %0, %1;" : "=r"(u) : "f"(x));
    return u;
}

__device__ __forceinline__ void cp_async16(float* smem_dst, const float* gsrc, bool pred) {
    uint32_t s = (uint32_t)__cvta_generic_to_shared(smem_dst);
    int sz = pred ? 16 : 0;
    asm volatile("cp.async.cg.shared.global [%0], [%1], 16, %2;\n"
                 :: "r"(s), "l"(gsrc), "r"(sz));
}

__global__ __launch_bounds__(256, 1) void gemm_tf32_k(
    const float* __restrict__ A, const float* __restrict__ B,
    const float* __restrict__ bias, float* __restrict__ C,
    const float* __restrict__ dinvv, int M, int K, int relu_flag) {
    extern __shared__ float sm[];

    int tid = threadIdx.x;
    int warp = tid >> 5;
    int lane = tid & 31;
    int grp = lane >> 2;   // 0..7
    int tig = lane & 3;    // 0..3
    int wm = warp >> 2;    // 0..1
    int wn = warp & 3;     // 0..3
    int bm = blockIdx.x * 128;
    int ntiles = K >> 5;

    float c[4][8][4];
#pragma unroll
    for (int mt = 0; mt < 4; mt++)
#pragma unroll
        for (int nt = 0; nt < 8; nt++)
#pragma unroll
            for (int q = 0; q < 4; q++) c[mt][nt][q] = 0.0f;

    // staging: issue cp.async for tile t into buffer buf
    auto stage = [&](int t, int buf) {
        float* As = sm + buf * STAGE_FLOATS;
        float* Bs = As + 128 * AS_STRIDE;
        int k0 = t << 5;
#pragma unroll
        for (int i = 0; i < 4; i++) {
            int ci = tid + i * 256;
            int row = ci >> 3;
            int col4 = (ci & 7) << 2;
            int gm = bm + row;
            bool ok = gm < M;
            int gms = ok ? gm : (M - 1);
            cp_async16(As + row * AS_STRIDE + col4, A + (size_t)gms * K + k0 + col4, ok);
        }
#pragma unroll
        for (int i = 0; i < 8; i++) {
            int ci = tid + i * 256;
            int row = ci >> 6;
            int col4 = (ci & 63) << 2;
            cp_async16(Bs + row * BS_STRIDE + col4, B + (size_t)(k0 + row) * 256 + col4, true);
        }
        asm volatile("cp.async.commit_group;\n");
    };

    stage(0, 0);

    for (int t = 0; t < ntiles; t++) {
        if (t + 1 < ntiles) {
            stage(t + 1, (t + 1) & 1);
            asm volatile("cp.async.wait_group 1;\n");
        } else {
            asm volatile("cp.async.wait_group 0;\n");
        }
        __syncthreads();

        float* As = sm + (t & 1) * STAGE_FLOATS;
        float* Bs = As + 128 * AS_STRIDE;

#pragma unroll
        for (int ks = 0; ks < 4; ks++) {
            int kk = ks << 3;
            uint32_t af[4][4];
#pragma unroll
            for (int mt = 0; mt < 4; mt++) {
                int r0 = wm * 64 + mt * 16 + grp;
                af[mt][0] = tf32bits(As[r0 * AS_STRIDE + kk + tig]);
                af[mt][1] = tf32bits(As[(r0 + 8) * AS_STRIDE + kk + tig]);
                af[mt][2] = tf32bits(As[r0 * AS_STRIDE + kk + tig + 4]);
                af[mt][3] = tf32bits(As[(r0 + 8) * AS_STRIDE + kk + tig + 4]);
            }
#pragma unroll
            for (int nt = 0; nt < 8; nt++) {
                int col = wn * 64 + nt * 8 + grp;
                uint32_t b0 = tf32bits(Bs[(kk + tig) * BS_STRIDE + col]);
                uint32_t b1 = tf32bits(Bs[(kk + tig + 4) * BS_STRIDE + col]);
#pragma unroll
                for (int mt = 0; mt < 4; mt++) {
                    asm volatile(
                        "mma.sync.aligned.m16n8k8.row.col.f32.tf32.tf32.f32 "
                        "{%0,%1,%2,%3},{%4,%5,%6,%7},{%8,%9},{%0,%1,%2,%3};\n"
                        : "+f"(c[mt][nt][0]), "+f"(c[mt][nt][1]),
                          "+f"(c[mt][nt][2]), "+f"(c[mt][nt][3])
                        : "r"(af[mt][0]), "r"(af[mt][1]), "r"(af[mt][2]), "r"(af[mt][3]),
                          "r"(b0), "r"(b1));
                }
            }
        }
        __syncthreads();
    }

    // epilogue
#pragma unroll
    for (int mt = 0; mt < 4; mt++) {
        int r0 = bm + wm * 64 + mt * 16 + grp;
        int r1 = r0 + 8;
        float d0 = 1.0f, d1 = 1.0f;
        if (dinvv) {
            if (r0 < M) d0 = dinvv[r0];
            if (r1 < M) d1 = dinvv[r1];
        }
#pragma unroll
        for (int nt = 0; nt < 8; nt++) {
            int col = wn * 64 + nt * 8 + 2 * tig;
            float b0f = 0.f, b1f = 0.f;
            if (bias) { b0f = bias[col]; b1f = bias[col + 1]; }
            float v0 = c[mt][nt][0] + b0f;
            float v1 = c[mt][nt][1] + b1f;
            float v2 = c[mt][nt][2] + b0f;
            float v3 = c[mt][nt][3] + b1f;
            if (relu_flag) {
                v0 = fmaxf(v0, 0.f); v1 = fmaxf(v1, 0.f);
                v2 = fmaxf(v2, 0.f); v3 = fmaxf(v3, 0.f);
            }
            v0 *= d0; v1 *= d0; v2 *= d1; v3 *= d1;
            if (r0 < M) *(float2*)(C + (size_t)r0 * 256 + col) = make_float2(v0, v1);
            if (r1 < M) *(float2*)(C + (size_t)r1 * 256 + col) = make_float2(v2, v3);
        }
    }
}

// ---------------- CSR aggregate + finalize fused ----------------
// h[d] = relu(dinv[d] * (g[d] + sum_{s in adj[d]} g[s]) + bias)
__global__ void aggregate_k(const int* __restrict__ off, const int* __restrict__ adj,
                            const float* __restrict__ g, const float* __restrict__ dinv,
                            const float* __restrict__ bias, float* __restrict__ h) {
    int gw = (blockIdx.x * blockDim.x + threadIdx.x) >> 5;
    if (gw >= NNODES * 2) return;
    int node = gw >> 1;
    int lane = threadIdx.x & 31;
    int col = ((gw & 1) << 7) + (lane << 2);

    float4 acc = *(const float4*)(g + (size_t)node * HID + col);  // self loop
    int e0 = off[node], e1 = off[node + 1];
    for (int j = e0; j < e1; j++) {
        int s = adj[j];
        float4 v = *(const float4*)(g + (size_t)s * HID + col);
        acc.x += v.x; acc.y += v.y; acc.z += v.z; acc.w += v.w;
    }
    float dv = dinv[node];
    float4 o;
    o.x = fmaxf(fmaf(acc.x, dv, bias[col + 0]), 0.f);
    o.y = fmaxf(fmaf(acc.y, dv, bias[col + 1]), 0.f);
    o.z = fmaxf(fmaf(acc.z, dv, bias[col + 2]), 0.f);
    o.w = fmaxf(fmaf(acc.w, dv, bias[col + 3]), 0.f);
    *(float4*)(h + (size_t)node * HID + col) = o;
}

// ---------------- pooling partials ----------------
__global__ void pool_partial_k(const float* __restrict__ h, float* __restrict__ psum,
                               float* __restrict__ pmax) {
    int col = threadIdx.x;  // 256
    int b = blockIdx.x;     // PB
    float s = 0.0f, m = -1e30f;
    for (int r = b; r < NNODES; r += PB) {
        float v = h[(size_t)r * HID + col];
        s += v;
        m = fmaxf(m, v);
    }
    psum[b * HID + col] = s;
    pmax[b * HID + col] = m;
}

// ---------------- head ----------------
__global__ void head_k(const float* __restrict__ psum, const float* __restrict__ pmax,
                       const float* __restrict__ Wg1, const float* __restrict__ bg1,
                       const float* __restrict__ Wg2, const float* __restrict__ bg2,
                       const float* __restrict__ Wd1, const float* __restrict__ bd1,
                       const float* __restrict__ Wd2, const float* __restrict__ bd2,
                       float* __restrict__ out, float* __restrict__ prob) {
    __shared__ float rep[2 * HID];
    __shared__ float u1[HID];
    __shared__ float ge[EMB];
    __shared__ float v1[HID];
    __shared__ float vv[HID];
    __shared__ float red[HID];
    int t = threadIdx.x;  // 512

    if (t < HID) {
        float s = 0.0f;
        for (int i = 0; i < PB; i++) s += psum[i * HID + t];
        rep[t] = s * (1.0f / NNODES);
    } else {
        int c = t - HID;
        float m = -1e30f;
        for (int i = 0; i < PB; i++) m = fmaxf(m, pmax[i * HID + c]);
        rep[HID + c] = m;
    }
    __syncthreads();

    if (t < HID) {
        float s = bg1[t];
        for (int k = 0; k < 2 * HID; k++) s += rep[k] * Wg1[k * HID + t];
        u1[t] = fmaxf(s, 0.0f);
    }
    __syncthreads();

    if (t < EMB) {
        float s = bg2[t];
        for (int k = 0; k < HID; k++) s += u1[k] * Wg2[k * EMB + t];
        ge[t] = s;
        out[t] = s;
    }
    __syncthreads();

    if (t < HID) {
        float s = bd1[t];
        for (int k = 0; k < EMB; k++) s += ge[k] * Wd1[k * HID + t];
        v1[t] = fmaxf(s, 0.0f);
    }
    __syncthreads();

    if (t < HID) {
        float s = bd2[t];
        for (int k = 0; k < HID; k++) s += v1[k] * Wd2[k * HID + t];
        vv[t] = s;
    }
    __syncthreads();

    if (t < HID) red[t] = vv[t] * vv[t];
    __syncthreads();
    for (int s = HID / 2; s > 0; s >>= 1) {
        if (t < s) red[t] += red[t + s];
        __syncthreads();
    }
    if (t == 0) *prob = 1.0f / (1.0f + expf(-red[0]));
}

__global__ void fill_probs_k(float* __restrict__ out, const float* __restrict__ prob, int E) {
    int i = blockIdx.x * blockDim.x + threadIdx.x;
    float p = *prob;
    int base = i << 2;
    if (base + 3 < E) {
        *(float4*)(out + EMB + base) = make_float4(p, p, p, p);
    } else {
        for (int j = base; j < E; j++) out[EMB + j] = p;
    }
}

// ---------------- launch ----------------
extern "C" void kernel_launch(void* const* d_in, const int* in_sizes, int n_in,
                              void* d_out, int out_size) {
    const float* x = (const float*)d_in[0];
    const void* ei = d_in[1];
    const float* W1 = (const float*)d_in[2];
    const float* b1 = (const float*)d_in[3];
    const float* W2 = (const float*)d_in[4];
    const float* b2 = (const float*)d_in[5];
    const float* convW = (const float*)d_in[6];
    const float* convb = (const float*)d_in[7];
    const float* Wg1 = (const float*)d_in[8];
    const float* bg1 = (const float*)d_in[9];
    const float* Wg2 = (const float*)d_in[10];
    const float* bg2 = (const float*)d_in[11];
    const float* Wd1 = (const float*)d_in[12];
    const float* bd1 = (const float*)d_in[13];
    const float* Wd2 = (const float*)d_in[14];
    const float* bd2 = (const float*)d_in[15];

    int E = in_sizes[1] / 2;

    float *h, *t1, *g, *dinv, *psum, *pmax, *prob;
    int *src, *dst, *cnt, *cursor, *off, *adj, *bsum, *flag;
    cudaGetSymbolAddress((void**)&h, g_h);
    cudaGetSymbolAddress((void**)&t1, g_t1);
    cudaGetSymbolAddress((void**)&g, g_g);
    cudaGetSymbolAddress((void**)&dinv, g_dinv);
    cudaGetSymbolAddress((void**)&psum, g_psum);
    cudaGetSymbolAddress((void**)&pmax, g_pmax);
    cudaGetSymbolAddress((void**)&prob, g_prob);
    cudaGetSymbolAddress((void**)&src, g_src);
    cudaGetSymbolAddress((void**)&dst, g_dst);
    cudaGetSymbolAddress((void**)&cnt, g_cnt);
    cudaGetSymbolAddress((void**)&cursor, g_cursor);
    cudaGetSymbolAddress((void**)&off, g_off);
    cudaGetSymbolAddress((void**)&adj, g_adj);
    cudaGetSymbolAddress((void**)&bsum, g_bsum);
    cudaGetSymbolAddress((void**)&flag, g_flag);

    cudaFuncSetAttribute(gemm_tf32_k, cudaFuncAttributeMaxDynamicSharedMemorySize, GEMM_SMEM);

    // Launch order chosen so ncu (-s 5 -c 1) profiles gemm2 (K=256).
    set_flag_k<<<1, 1>>>(flag);                                                    // 0
    zero2_k<<<(NNODES + 255) / 256, 256>>>(cnt, cursor, NNODES);                   // 1
    detect_k<<<16, 256>>>((const int*)ei, flag);                                   // 2
    gemm_tf32_k<<<NB_M, 256, GEMM_SMEM>>>(x, W1, b1, t1, nullptr, NNODES, 64, 1);  // 3
    convert_edges_k<<<(E + 255) / 256, 256>>>(ei, flag, src, dst, cnt, E);         // 4
    gemm_tf32_k<<<NB_M, 256, GEMM_SMEM>>>(t1, W2, b2, h, nullptr, NNODES, HID, 0); // 5

    // CSR finish
    dinv_k<<<(NNODES + 255) / 256, 256>>>(cnt, dinv);
    scan1_k<<<SCAN_B, 256>>>(cnt, bsum);
    scan2_k<<<1, 32>>>(bsum);
    scan3_k<<<SCAN_B, 256>>>(cnt, bsum, off);
    fill_k<<<(E + 255) / 256, 256>>>(src, dst, off, cursor, adj, E);

    // GCN layers
    int agg_blocks = (NNODES * 2 * 32 + 255) / 256;
    for (int l = 0; l < 3; l++) {
        gemm_tf32_k<<<NB_M, 256, GEMM_SMEM>>>(h, convW + (size_t)l * HID * HID, nullptr, g,
                                              dinv, NNODES, HID, 0);
        aggregate_k<<<agg_blocks, 256>>>(off, adj, g, dinv, convb + (size_t)l * HID, h);
    }

    // pooling + heads + output
    pool_partial_k<<<PB, 256>>>(h, psum, pmax);
    head_k<<<1, 512>>>(psum, pmax, Wg1, bg1, Wg2, bg2, Wd1, bd1, Wd2, bd2, (float*)d_out, prob);
    fill_probs_k<<<(E / 4 + 255) / 256, 256>>>((float*)d_out, prob, E);
}

// round 5
// speedup vs baseline: 4.6525x; 1.0755x over previous
#include <cuda_runtime.h>
#include <cuda_fp16.h>
#include <math.h>
#include <stdint.h>

#define NNODES 50000
#define HID 256
#define EMB 128
#define EMAX 800000
#define PB 120
#define NB_M 391   // ceil(50000/128)
#define SCAN_B 196 // ceil(50000/256)

// ---- scratch (static device globals: no allocation allowed) ----
__device__ float g_h[NNODES * HID];
__device__ float g_t1[NNODES * HID];
__device__ __half g_gh[NNODES * HID];
__device__ float g_dinv[NNODES];
__device__ float g_psum[PB * HID];
__device__ float g_pmax[PB * HID];
__device__ float g_prob;
__device__ int g_src[EMAX];
__device__ int g_dst[EMAX];
__device__ int g_cnt[NNODES];
__device__ int g_cursor[NNODES];
__device__ int g_off[NNODES + 1];
__device__ int g_adj[EMAX];
__device__ int g_bsum[SCAN_B];
__device__ int g_flag;

// ---------------- small utility kernels ----------------
__global__ void set_flag_k(int* flag) { *flag = 1; }

__global__ void zero2_k(int* a, int* b, int n) {
    int i = blockIdx.x * blockDim.x + threadIdx.x;
    if (i < n) { a[i] = 0; b[i] = 0; }
}

// int64-vs-int32 sniff: int64 LE indices < 50000 have all odd words zero
__global__ void detect_k(const int* p, int* flag) {
    int i = blockIdx.x * blockDim.x + threadIdx.x;  // 4096 checks
    if (p[2 * i + 1] != 0) *flag = 0;
}

// convert + degree count fused
__global__ void convert_edges_k(const void* ei, const int* flag, int* src, int* dst,
                                int* cnt, int E) {
    int i = blockIdx.x * blockDim.x + threadIdx.x;
    if (i >= E) return;
    int s, d;
    if (*flag) {
        const long long* p = (const long long*)ei;
        s = (int)p[i];
        d = (int)p[E + i];
    } else {
        const int* p = (const int*)ei;
        s = p[i];
        d = p[E + i];
    }
    src[i] = s;
    dst[i] = d;
    atomicAdd(&cnt[d], 1);
}

__global__ void dinv_k(const int* __restrict__ cnt, float* __restrict__ dinv) {
    int i = blockIdx.x * blockDim.x + threadIdx.x;
    if (i < NNODES) dinv[i] = rsqrtf((float)cnt[i] + 1.0f);
}

// ---------------- CSR scan + fill ----------------
__global__ void scan1_k(const int* __restrict__ cnt, int* __restrict__ bsum) {
    __shared__ int s[256];
    int t = threadIdx.x;
    int i = blockIdx.x * 256 + t;
    s[t] = (i < NNODES) ? cnt[i] : 0;
    __syncthreads();
    for (int d = 128; d > 0; d >>= 1) {
        if (t < d) s[t] += s[t + d];
        __syncthreads();
    }
    if (t == 0) bsum[blockIdx.x] = s[0];
}

__global__ void scan2_k(int* bsum) {
    if (threadIdx.x == 0) {
        int run = 0;
        for (int b = 0; b < SCAN_B; b++) {
            int v = bsum[b];
            bsum[b] = run;
            run += v;
        }
    }
}

__global__ void scan3_k(const int* __restrict__ cnt, const int* __restrict__ bsum,
                        int* __restrict__ off) {
    __shared__ int s[256];
    int t = threadIdx.x;
    int i = blockIdx.x * 256 + t;
    int val = (i < NNODES) ? cnt[i] : 0;
    s[t] = val;
    __syncthreads();
    for (int d = 1; d < 256; d <<= 1) {
        int tmp = (t >= d) ? s[t - d] : 0;
        __syncthreads();
        s[t] += tmp;
        __syncthreads();
    }
    if (i <= NNODES) off[i] = bsum[blockIdx.x] + s[t] - val;
}

__global__ void fill_k(const int* __restrict__ src, const int* __restrict__ dst,
                       const int* __restrict__ off, int* __restrict__ cursor,
                       int* __restrict__ adj, int E) {
    int i = blockIdx.x * blockDim.x + threadIdx.x;
    if (i >= E) return;
    int d = dst[i];
    int p = atomicAdd(&cursor[d], 1);
    adj[off[d] + p] = src[i];
}

// ---------------- TF32 tensor-core GEMM, cp.async double-buffered ----------------
// Block tile 128x256x32, 8 warps of 64x64, mma.m16n8k8.tf32, 2-stage pipeline.
// Output: fp32 C (encoder) or fp16 Ch (conv layers, pre-scaled by dinv).
#define AS_STRIDE 36
#define BS_STRIDE 264
#define STAGE_FLOATS (128 * AS_STRIDE + 32 * BS_STRIDE)
#define GEMM_SMEM (2 * STAGE_FLOATS * 4)

__device__ __forceinline__ uint32_t tf32bits(float x) {
    uint32_t u;
    asm("cvt.rna.tf32.f32 %0, %1;" : "=r"(u) : "f"(x));
    return u;
}

__device__ __forceinline__ void cp_async16(float* smem_dst, const float* gsrc, bool pred) {
    uint32_t s = (uint32_t)__cvta_generic_to_shared(smem_dst);
    int sz = pred ? 16 : 0;
    asm volatile("cp.async.cg.shared.global [%0], [%1], 16, %2;\n"
                 :: "r"(s), "l"(gsrc), "r"(sz));
}

__global__ __launch_bounds__(256, 1) void gemm_tf32_k(
    const float* __restrict__ A, const float* __restrict__ B,
    const float* __restrict__ bias, float* __restrict__ C,
    __half* __restrict__ Ch, const float* __restrict__ dinvv,
    int M, int K, int relu_flag) {
    extern __shared__ float sm[];

    int tid = threadIdx.x;
    int warp = tid >> 5;
    int lane = tid & 31;
    int grp = lane >> 2;   // 0..7
    int tig = lane & 3;    // 0..3
    int wm = warp >> 2;    // 0..1
    int wn = warp & 3;     // 0..3
    int bm = blockIdx.x * 128;
    int ntiles = K >> 5;

    float c[4][8][4];
#pragma unroll
    for (int mt = 0; mt < 4; mt++)
#pragma unroll
        for (int nt = 0; nt < 8; nt++)
#pragma unroll
            for (int q = 0; q < 4; q++) c[mt][nt][q] = 0.0f;

    auto stage = [&](int t, int buf) {
        float* As = sm + buf * STAGE_FLOATS;
        float* Bs = As + 128 * AS_STRIDE;
        int k0 = t << 5;
#pragma unroll
        for (int i = 0; i < 4; i++) {
            int ci = tid + i * 256;
            int row = ci >> 3;
            int col4 = (ci & 7) << 2;
            int gm = bm + row;
            bool ok = gm < M;
            int gms = ok ? gm : (M - 1);
            cp_async16(As + row * AS_STRIDE + col4, A + (size_t)gms * K + k0 + col4, ok);
        }
#pragma unroll
        for (int i = 0; i < 8; i++) {
            int ci = tid + i * 256;
            int row = ci >> 6;
            int col4 = (ci & 63) << 2;
            cp_async16(Bs + row * BS_STRIDE + col4, B + (size_t)(k0 + row) * 256 + col4, true);
        }
        asm volatile("cp.async.commit_group;\n");
    };

    stage(0, 0);

    for (int t = 0; t < ntiles; t++) {
        if (t + 1 < ntiles) {
            stage(t + 1, (t + 1) & 1);
            asm volatile("cp.async.wait_group 1;\n");
        } else {
            asm volatile("cp.async.wait_group 0;\n");
        }
        __syncthreads();

        float* As = sm + (t & 1) * STAGE_FLOATS;
        float* Bs = As + 128 * AS_STRIDE;

#pragma unroll
        for (int ks = 0; ks < 4; ks++) {
            int kk = ks << 3;
            uint32_t af[4][4];
#pragma unroll
            for (int mt = 0; mt < 4; mt++) {
                int r0 = wm * 64 + mt * 16 + grp;
                af[mt][0] = tf32bits(As[r0 * AS_STRIDE + kk + tig]);
                af[mt][1] = tf32bits(As[(r0 + 8) * AS_STRIDE + kk + tig]);
                af[mt][2] = tf32bits(As[r0 * AS_STRIDE + kk + tig + 4]);
                af[mt][3] = tf32bits(As[(r0 + 8) * AS_STRIDE + kk + tig + 4]);
            }
#pragma unroll
            for (int nt = 0; nt < 8; nt++) {
                int col = wn * 64 + nt * 8 + grp;
                uint32_t b0 = tf32bits(Bs[(kk + tig) * BS_STRIDE + col]);
                uint32_t b1 = tf32bits(Bs[(kk + tig + 4) * BS_STRIDE + col]);
#pragma unroll
                for (int mt = 0; mt < 4; mt++) {
                    asm volatile(
                        "mma.sync.aligned.m16n8k8.row.col.f32.tf32.tf32.f32 "
                        "{%0,%1,%2,%3},{%4,%5,%6,%7},{%8,%9},{%0,%1,%2,%3};\n"
                        : "+f"(c[mt][nt][0]), "+f"(c[mt][nt][1]),
                          "+f"(c[mt][nt][2]), "+f"(c[mt][nt][3])
                        : "r"(af[mt][0]), "r"(af[mt][1]), "r"(af[mt][2]), "r"(af[mt][3]),
                          "r"(b0), "r"(b1));
                }
            }
        }
        __syncthreads();
    }

    // epilogue
#pragma unroll
    for (int mt = 0; mt < 4; mt++) {
        int r0 = bm + wm * 64 + mt * 16 + grp;
        int r1 = r0 + 8;
        float d0 = 1.0f, d1 = 1.0f;
        if (dinvv) {
            if (r0 < M) d0 = dinvv[r0];
            if (r1 < M) d1 = dinvv[r1];
        }
#pragma unroll
        for (int nt = 0; nt < 8; nt++) {
            int col = wn * 64 + nt * 8 + 2 * tig;
            float b0f = 0.f, b1f = 0.f;
            if (bias) { b0f = bias[col]; b1f = bias[col + 1]; }
            float v0 = c[mt][nt][0] + b0f;
            float v1 = c[mt][nt][1] + b1f;
            float v2 = c[mt][nt][2] + b0f;
            float v3 = c[mt][nt][3] + b1f;
            if (relu_flag) {
                v0 = fmaxf(v0, 0.f); v1 = fmaxf(v1, 0.f);
                v2 = fmaxf(v2, 0.f); v3 = fmaxf(v3, 0.f);
            }
            v0 *= d0; v1 *= d0; v2 *= d1; v3 *= d1;
            if (Ch) {
                if (r0 < M) *(__half2*)(Ch + (size_t)r0 * 256 + col) = __floats2half2_rn(v0, v1);
                if (r1 < M) *(__half2*)(Ch + (size_t)r1 * 256 + col) = __floats2half2_rn(v2, v3);
            } else {
                if (r0 < M) *(float2*)(C + (size_t)r0 * 256 + col) = make_float2(v0, v1);
                if (r1 < M) *(float2*)(C + (size_t)r1 * 256 + col) = make_float2(v2, v3);
            }
        }
    }
}

// ---------------- CSR aggregate (fp16 gather) + finalize fused ----------------
// h[d] = relu(dinv[d] * (g[d] + sum_{s in adj[d]} g[s]) + bias); g in fp16.
// One warp per node; each lane owns 8 contiguous halves (16B uint4 per read).
__global__ void aggregate_h_k(const int* __restrict__ off, const int* __restrict__ adj,
                              const __half* __restrict__ g, const float* __restrict__ dinv,
                              const float* __restrict__ bias, float* __restrict__ h) {
    int node = (blockIdx.x * blockDim.x + threadIdx.x) >> 5;
    if (node >= NNODES) return;
    int lane = threadIdx.x & 31;
    int col = lane << 3;  // 8 halves per lane

    float acc[8];
    {
        uint4 v = *(const uint4*)(g + (size_t)node * HID + col);  // self loop
        const __half2* p = (const __half2*)&v;
#pragma unroll
        for (int q = 0; q < 4; q++) {
            float2 f = __half22float2(p[q]);
            acc[2 * q] = f.x;
            acc[2 * q + 1] = f.y;
        }
    }
    int e0 = off[node], e1 = off[node + 1];
    for (int j = e0; j < e1; j++) {
        int s = adj[j];
        uint4 v = *(const uint4*)(g + (size_t)s * HID + col);
        const __half2* p = (const __half2*)&v;
#pragma unroll
        for (int q = 0; q < 4; q++) {
            float2 f = __half22float2(p[q]);
            acc[2 * q] += f.x;
            acc[2 * q + 1] += f.y;
        }
    }
    float dv = dinv[node];
    float4 o0, o1;
    o0.x = fmaxf(fmaf(acc[0], dv, bias[col + 0]), 0.f);
    o0.y = fmaxf(fmaf(acc[1], dv, bias[col + 1]), 0.f);
    o0.z = fmaxf(fmaf(acc[2], dv, bias[col + 2]), 0.f);
    o0.w = fmaxf(fmaf(acc[3], dv, bias[col + 3]), 0.f);
    o1.x = fmaxf(fmaf(acc[4], dv, bias[col + 4]), 0.f);
    o1.y = fmaxf(fmaf(acc[5], dv, bias[col + 5]), 0.f);
    o1.z = fmaxf(fmaf(acc[6], dv, bias[col + 6]), 0.f);
    o1.w = fmaxf(fmaf(acc[7], dv, bias[col + 7]), 0.f);
    *(float4*)(h + (size_t)node * HID + col) = o0;
    *(float4*)(h + (size_t)node * HID + col + 4) = o1;
}

// ---------------- pooling partials ----------------
__global__ void pool_partial_k(const float* __restrict__ h, float* __restrict__ psum,
                               float* __restrict__ pmax) {
    int col = threadIdx.x;  // 256
    int b = blockIdx.x;     // PB
    float s = 0.0f, m = -1e30f;
    for (int r = b; r < NNODES; r += PB) {
        float v = h[(size_t)r * HID + col];
        s += v;
        m = fmaxf(m, v);
    }
    psum[b * HID + col] = s;
    pmax[b * HID + col] = m;
}

// ---------------- head ----------------
__global__ void head_k(const float* __restrict__ psum, const float* __restrict__ pmax,
                       const float* __restrict__ Wg1, const float* __restrict__ bg1,
                       const float* __restrict__ Wg2, const float* __restrict__ bg2,
                       const float* __restrict__ Wd1, const float* __restrict__ bd1,
                       const float* __restrict__ Wd2, const float* __restrict__ bd2,
                       float* __restrict__ out, float* __restrict__ prob) {
    __shared__ float rep[2 * HID];
    __shared__ float u1[HID];
    __shared__ float ge[EMB];
    __shared__ float v1[HID];
    __shared__ float vv[HID];
    __shared__ float red[HID];
    int t = threadIdx.x;  // 512

    if (t < HID) {
        float s = 0.0f;
        for (int i = 0; i < PB; i++) s += psum[i * HID + t];
        rep[t] = s * (1.0f / NNODES);
    } else {
        int c = t - HID;
        float m = -1e30f;
        for (int i = 0; i < PB; i++) m = fmaxf(m, pmax[i * HID + c]);
        rep[HID + c] = m;
    }
    __syncthreads();

    if (t < HID) {
        float s = bg1[t];
        for (int k = 0; k < 2 * HID; k++) s += rep[k] * Wg1[k * HID + t];
        u1[t] = fmaxf(s, 0.0f);
    }
    __syncthreads();

    if (t < EMB) {
        float s = bg2[t];
        for (int k = 0; k < HID; k++) s += u1[k] * Wg2[k * EMB + t];
        ge[t] = s;
        out[t] = s;
    }
    __syncthreads();

    if (t < HID) {
        float s = bd1[t];
        for (int k = 0; k < EMB; k++) s += ge[k] * Wd1[k * HID + t];
        v1[t] = fmaxf(s, 0.0f);
    }
    __syncthreads();

    if (t < HID) {
        float s = bd2[t];
        for (int k = 0; k < HID; k++) s += v1[k] * Wd2[k * HID + t];
        vv[t] = s;
    }
    __syncthreads();

    if (t < HID) red[t] = vv[t] * vv[t];
    __syncthreads();
    for (int s = HID / 2; s > 0; s >>= 1) {
        if (t < s) red[t] += red[t + s];
        __syncthreads();
    }
    if (t == 0) *prob = 1.0f / (1.0f + expf(-red[0]));
}

__global__ void fill_probs_k(float* __restrict__ out, const float* __restrict__ prob, int E) {
    int i = blockIdx.x * blockDim.x + threadIdx.x;
    float p = *prob;
    int base = i << 2;
    if (base + 3 < E) {
        *(float4*)(out + EMB + base) = make_float4(p, p, p, p);
    } else {
        for (int j = base; j < E; j++) out[EMB + j] = p;
    }
}

// ---------------- launch ----------------
extern "C" void kernel_launch(void* const* d_in, const int* in_sizes, int n_in,
                              void* d_out, int out_size) {
    const float* x = (const float*)d_in[0];
    const void* ei = d_in[1];
    const float* W1 = (const float*)d_in[2];
    const float* b1 = (const float*)d_in[3];
    const float* W2 = (const float*)d_in[4];
    const float* b2 = (const float*)d_in[5];
    const float* convW = (const float*)d_in[6];
    const float* convb = (const float*)d_in[7];
    const float* Wg1 = (const float*)d_in[8];
    const float* bg1 = (const float*)d_in[9];
    const float* Wg2 = (const float*)d_in[10];
    const float* bg2 = (const float*)d_in[11];
    const float* Wd1 = (const float*)d_in[12];
    const float* bd1 = (const float*)d_in[13];
    const float* Wd2 = (const float*)d_in[14];
    const float* bd2 = (const float*)d_in[15];

    int E = in_sizes[1] / 2;

    float *h, *t1, *dinv, *psum, *pmax, *prob;
    __half* gh;
    int *src, *dst, *cnt, *cursor, *off, *adj, *bsum, *flag;
    cudaGetSymbolAddress((void**)&h, g_h);
    cudaGetSymbolAddress((void**)&t1, g_t1);
    cudaGetSymbolAddress((void**)&gh, g_gh);
    cudaGetSymbolAddress((void**)&dinv, g_dinv);
    cudaGetSymbolAddress((void**)&psum, g_psum);
    cudaGetSymbolAddress((void**)&pmax, g_pmax);
    cudaGetSymbolAddress((void**)&prob, g_prob);
    cudaGetSymbolAddress((void**)&src, g_src);
    cudaGetSymbolAddress((void**)&dst, g_dst);
    cudaGetSymbolAddress((void**)&cnt, g_cnt);
    cudaGetSymbolAddress((void**)&cursor, g_cursor);
    cudaGetSymbolAddress((void**)&off, g_off);
    cudaGetSymbolAddress((void**)&adj, g_adj);
    cudaGetSymbolAddress((void**)&bsum, g_bsum);
    cudaGetSymbolAddress((void**)&flag, g_flag);

    cudaFuncSetAttribute(gemm_tf32_k, cudaFuncAttributeMaxDynamicSharedMemorySize, GEMM_SMEM);

    set_flag_k<<<1, 1>>>(flag);                                                             // 0
    zero2_k<<<(NNODES + 255) / 256, 256>>>(cnt, cursor, NNODES);                            // 1
    detect_k<<<16, 256>>>((const int*)ei, flag);                                            // 2
    gemm_tf32_k<<<NB_M, 256, GEMM_SMEM>>>(x, W1, b1, t1, nullptr, nullptr, NNODES, 64, 1);  // 3
    convert_edges_k<<<(E + 255) / 256, 256>>>(ei, flag, src, dst, cnt, E);                  // 4
    gemm_tf32_k<<<NB_M, 256, GEMM_SMEM>>>(t1, W2, b2, h, nullptr, nullptr, NNODES, HID, 0); // 5

    // CSR finish
    dinv_k<<<(NNODES + 255) / 256, 256>>>(cnt, dinv);
    scan1_k<<<SCAN_B, 256>>>(cnt, bsum);
    scan2_k<<<1, 32>>>(bsum);
    scan3_k<<<SCAN_B, 256>>>(cnt, bsum, off);
    fill_k<<<(E + 255) / 256, 256>>>(src, dst, off, cursor, adj, E);

    // GCN layers: gemm writes fp16 g (scaled by dinv); aggregate gathers fp16
    int agg_blocks = (NNODES * 32 + 255) / 256;
    for (int l = 0; l < 3; l++) {
        gemm_tf32_k<<<NB_M, 256, GEMM_SMEM>>>(h, convW + (size_t)l * HID * HID, nullptr,
                                              nullptr, gh, dinv, NNODES, HID, 0);
        aggregate_h_k<<<agg_blocks, 256>>>(off, adj, gh, dinv, convb + (size_t)l * HID, h);
    }

    // pooling + heads + output
    pool_partial_k<<<PB, 256>>>(h, psum, pmax);
    head_k<<<1, 512>>>(psum, pmax, Wg1, bg1, Wg2, bg2, Wd1, bd1, Wd2, bd2, (float*)d_out, prob);
    fill_probs_k<<<(E / 4 + 255) / 256, 256>>>((float*)d_out, prob, E);
}

// round 6
// speedup vs baseline: 4.7252x; 1.0156x over previous
#include <cuda_runtime.h>
#include <cuda_fp16.h>
#include <math.h>
#include <stdint.h>

#define NNODES 50000
#define HID 256
#define EMB 128
#define EMAX 800000
#define PB 120
#define NB_M 391   // ceil(50000/128)
#define SCAN_B 196 // ceil(50000/256)

// ---- scratch (static device globals: no allocation allowed) ----
__device__ float g_h[NNODES * HID];
__device__ float g_t1[NNODES * HID];
__device__ __half g_gh[NNODES * HID];
__device__ float g_dinv[NNODES];
__device__ float g_psum[PB * HID];
__device__ float g_pmax[PB * HID];
__device__ float g_prob;
__device__ int g_src[EMAX];
__device__ int g_dst[EMAX];
__device__ int g_cnt[NNODES];
__device__ int g_cursor[NNODES];
__device__ int g_off[NNODES + 1];
__device__ int g_adj[EMAX];
__device__ int g_bsum[SCAN_B];
__device__ int g_flag;

// ---------------- small utility kernels ----------------
__global__ void set_flag_k(int* flag) { *flag = 1; }

__global__ void zero2_k(int* a, int* b, int n) {
    int i = blockIdx.x * blockDim.x + threadIdx.x;
    if (i < n) { a[i] = 0; b[i] = 0; }
}

// int64-vs-int32 sniff: int64 LE indices < 50000 have all odd words zero
__global__ void detect_k(const int* p, int* flag) {
    int i = blockIdx.x * blockDim.x + threadIdx.x;  // 4096 checks
    if (p[2 * i + 1] != 0) *flag = 0;
}

// convert + degree count fused
__global__ void convert_edges_k(const void* ei, const int* flag, int* src, int* dst,
                                int* cnt, int E) {
    int i = blockIdx.x * blockDim.x + threadIdx.x;
    if (i >= E) return;
    int s, d;
    if (*flag) {
        const long long* p = (const long long*)ei;
        s = (int)p[i];
        d = (int)p[E + i];
    } else {
        const int* p = (const int*)ei;
        s = p[i];
        d = p[E + i];
    }
    src[i] = s;
    dst[i] = d;
    atomicAdd(&cnt[d], 1);
}

__global__ void dinv_k(const int* __restrict__ cnt, float* __restrict__ dinv) {
    int i = blockIdx.x * blockDim.x + threadIdx.x;
    if (i < NNODES) dinv[i] = rsqrtf((float)cnt[i] + 1.0f);
}

// ---------------- CSR scan + fill ----------------
__global__ void scan1_k(const int* __restrict__ cnt, int* __restrict__ bsum) {
    __shared__ int s[256];
    int t = threadIdx.x;
    int i = blockIdx.x * 256 + t;
    s[t] = (i < NNODES) ? cnt[i] : 0;
    __syncthreads();
    for (int d = 128; d > 0; d >>= 1) {
        if (t < d) s[t] += s[t + d];
        __syncthreads();
    }
    if (t == 0) bsum[blockIdx.x] = s[0];
}

__global__ void scan2_k(int* bsum) {
    if (threadIdx.x == 0) {
        int run = 0;
        for (int b = 0; b < SCAN_B; b++) {
            int v = bsum[b];
            bsum[b] = run;
            run += v;
        }
    }
}

__global__ void scan3_k(const int* __restrict__ cnt, const int* __restrict__ bsum,
                        int* __restrict__ off) {
    __shared__ int s[256];
    int t = threadIdx.x;
    int i = blockIdx.x * 256 + t;
    int val = (i < NNODES) ? cnt[i] : 0;
    s[t] = val;
    __syncthreads();
    for (int d = 1; d < 256; d <<= 1) {
        int tmp = (t >= d) ? s[t - d] : 0;
        __syncthreads();
        s[t] += tmp;
        __syncthreads();
    }
    if (i <= NNODES) off[i] = bsum[blockIdx.x] + s[t] - val;
}

__global__ void fill_k(const int* __restrict__ src, const int* __restrict__ dst,
                       const int* __restrict__ off, int* __restrict__ cursor,
                       int* __restrict__ adj, int E) {
    int i = blockIdx.x * blockDim.x + threadIdx.x;
    if (i >= E) return;
    int d = dst[i];
    int p = atomicAdd(&cursor[d], 1);
    adj[off[d] + p] = src[i];
}

// ---------------- TF32 tensor-core GEMM, 3-stage cp.async, 2 CTA/SM ----------------
// Block tile 128x128x32, 8 warps of 32x64, mma.m16n8k8.tf32.
// Output: fp32 C (encoder) or fp16 Ch (conv layers, pre-scaled by dinv).
#define AS_STRIDE 36
#define BS_STRIDE 136
#define STAGE_FLOATS (128 * AS_STRIDE + 32 * BS_STRIDE)  // 8960
#define GEMM_SMEM (3 * STAGE_FLOATS * 4)                 // 107520

__device__ __forceinline__ uint32_t tf32bits(float x) {
    uint32_t u;
    asm("cvt.rna.tf32.f32 %0, %1;" : "=r"(u) : "f"(x));
    return u;
}

__device__ __forceinline__ void cp_async16(float* smem_dst, const float* gsrc, bool pred) {
    uint32_t s = (uint32_t)__cvta_generic_to_shared(smem_dst);
    int sz = pred ? 16 : 0;
    asm volatile("cp.async.cg.shared.global [%0], [%1], 16, %2;\n"
                 :: "r"(s), "l"(gsrc), "r"(sz));
}

__global__ __launch_bounds__(256, 2) void gemm_tf32_k(
    const float* __restrict__ A, const float* __restrict__ B,
    const float* __restrict__ bias, float* __restrict__ C,
    __half* __restrict__ Ch, const float* __restrict__ dinvv,
    int M, int K, int relu_flag) {
    extern __shared__ float sm[];

    int tid = threadIdx.x;
    int warp = tid >> 5;
    int lane = tid & 31;
    int grp = lane >> 2;   // 0..7
    int tig = lane & 3;    // 0..3
    int wm = warp >> 1;    // 0..3 -> m offset wm*32
    int wn = warp & 1;     // 0..1 -> n offset wn*64
    int bm = blockIdx.x * 128;
    int bn = blockIdx.y * 128;
    int ntiles = K >> 5;

    float c[2][8][4];
#pragma unroll
    for (int mt = 0; mt < 2; mt++)
#pragma unroll
        for (int nt = 0; nt < 8; nt++)
#pragma unroll
            for (int q = 0; q < 4; q++) c[mt][nt][q] = 0.0f;

    auto stage = [&](int t, int buf) {
        float* As = sm + buf * STAGE_FLOATS;
        float* Bs = As + 128 * AS_STRIDE;
        int k0 = t << 5;
        // A: 128 rows x 32 cols = 1024 float4, 4 per thread
#pragma unroll
        for (int i = 0; i < 4; i++) {
            int ci = tid + i * 256;
            int row = ci >> 3;
            int col4 = (ci & 7) << 2;
            int gm = bm + row;
            bool ok = gm < M;
            int gms = ok ? gm : (M - 1);
            cp_async16(As + row * AS_STRIDE + col4, A + (size_t)gms * K + k0 + col4, ok);
        }
        // B: 32 rows x 128 cols = 1024 float4, 4 per thread
#pragma unroll
        for (int i = 0; i < 4; i++) {
            int ci = tid + i * 256;
            int row = ci >> 5;
            int col4 = (ci & 31) << 2;
            cp_async16(Bs + row * BS_STRIDE + col4,
                       B + (size_t)(k0 + row) * 256 + bn + col4, true);
        }
        asm volatile("cp.async.commit_group;\n");
    };

    stage(0, 0);
    if (ntiles > 1) stage(1, 1);

    for (int t = 0; t < ntiles; t++) {
        if (t + 2 < ntiles) stage(t + 2, (t + 2) % 3);
        int staged = (t + 3 < ntiles) ? (t + 3) : ntiles;
        int pend = staged - t - 1;
        if (pend >= 2) asm volatile("cp.async.wait_group 2;\n");
        else if (pend == 1) asm volatile("cp.async.wait_group 1;\n");
        else asm volatile("cp.async.wait_group 0;\n");
        __syncthreads();

        float* As = sm + (t % 3) * STAGE_FLOATS;
        float* Bs = As + 128 * AS_STRIDE;

#pragma unroll
        for (int ks = 0; ks < 4; ks++) {
            int kk = ks << 3;
            uint32_t af[2][4];
#pragma unroll
            for (int mt = 0; mt < 2; mt++) {
                int r0 = wm * 32 + mt * 16 + grp;
                af[mt][0] = tf32bits(As[r0 * AS_STRIDE + kk + tig]);
                af[mt][1] = tf32bits(As[(r0 + 8) * AS_STRIDE + kk + tig]);
                af[mt][2] = tf32bits(As[r0 * AS_STRIDE + kk + tig + 4]);
                af[mt][3] = tf32bits(As[(r0 + 8) * AS_STRIDE + kk + tig + 4]);
            }
#pragma unroll
            for (int nt = 0; nt < 8; nt++) {
                int col = wn * 64 + nt * 8 + grp;
                uint32_t b0 = tf32bits(Bs[(kk + tig) * BS_STRIDE + col]);
                uint32_t b1 = tf32bits(Bs[(kk + tig + 4) * BS_STRIDE + col]);
#pragma unroll
                for (int mt = 0; mt < 2; mt++) {
                    asm volatile(
                        "mma.sync.aligned.m16n8k8.row.col.f32.tf32.tf32.f32 "
                        "{%0,%1,%2,%3},{%4,%5,%6,%7},{%8,%9},{%0,%1,%2,%3};\n"
                        : "+f"(c[mt][nt][0]), "+f"(c[mt][nt][1]),
                          "+f"(c[mt][nt][2]), "+f"(c[mt][nt][3])
                        : "r"(af[mt][0]), "r"(af[mt][1]), "r"(af[mt][2]), "r"(af[mt][3]),
                          "r"(b0), "r"(b1));
                }
            }
        }
        __syncthreads();
    }

    // epilogue
#pragma unroll
    for (int mt = 0; mt < 2; mt++) {
        int r0 = bm + wm * 32 + mt * 16 + grp;
        int r1 = r0 + 8;
        float d0 = 1.0f, d1 = 1.0f;
        if (dinvv) {
            if (r0 < M) d0 = dinvv[r0];
            if (r1 < M) d1 = dinvv[r1];
        }
#pragma unroll
        for (int nt = 0; nt < 8; nt++) {
            int col = bn + wn * 64 + nt * 8 + 2 * tig;
            float b0f = 0.f, b1f = 0.f;
            if (bias) { b0f = bias[col]; b1f = bias[col + 1]; }
            float v0 = c[mt][nt][0] + b0f;
            float v1 = c[mt][nt][1] + b1f;
            float v2 = c[mt][nt][2] + b0f;
            float v3 = c[mt][nt][3] + b1f;
            if (relu_flag) {
                v0 = fmaxf(v0, 0.f); v1 = fmaxf(v1, 0.f);
                v2 = fmaxf(v2, 0.f); v3 = fmaxf(v3, 0.f);
            }
            v0 *= d0; v1 *= d0; v2 *= d1; v3 *= d1;
            if (Ch) {
                if (r0 < M) *(__half2*)(Ch + (size_t)r0 * 256 + col) = __floats2half2_rn(v0, v1);
                if (r1 < M) *(__half2*)(Ch + (size_t)r1 * 256 + col) = __floats2half2_rn(v2, v3);
            } else {
                if (r0 < M) *(float2*)(C + (size_t)r0 * 256 + col) = make_float2(v0, v1);
                if (r1 < M) *(float2*)(C + (size_t)r1 * 256 + col) = make_float2(v2, v3);
            }
        }
    }
}

// ---------------- CSR aggregate (fp16 gather, 4-way unrolled) ----------------
// h[d] = relu(dinv[d] * (g[d] + sum_{s in adj[d]} g[s]) + bias); g in fp16.
// One warp per node; lane owns 8 contiguous halves (16B uint4 per gather).
__device__ __forceinline__ void acc_add(float* acc, uint4 v) {
    const __half2* p = (const __half2*)&v;
#pragma unroll
    for (int q = 0; q < 4; q++) {
        float2 f = __half22float2(p[q]);
        acc[2 * q] += f.x;
        acc[2 * q + 1] += f.y;
    }
}

__global__ void aggregate_h_k(const int* __restrict__ off, const int* __restrict__ adj,
                              const __half* __restrict__ g, const float* __restrict__ dinv,
                              const float* __restrict__ bias, float* __restrict__ h) {
    int node = (blockIdx.x * blockDim.x + threadIdx.x) >> 5;
    if (node >= NNODES) return;
    int lane = threadIdx.x & 31;
    int col = lane << 3;  // 8 halves per lane

    float acc[8];
    {
        uint4 v = *(const uint4*)(g + (size_t)node * HID + col);  // self loop
        const __half2* p = (const __half2*)&v;
#pragma unroll
        for (int q = 0; q < 4; q++) {
            float2 f = __half22float2(p[q]);
            acc[2 * q] = f.x;
            acc[2 * q + 1] = f.y;
        }
    }
    int e0 = off[node], e1 = off[node + 1];
    int j = e0;
    // 4-way unroll: 4 independent gathers in flight
    for (; j + 4 <= e1; j += 4) {
        int s0 = adj[j], s1 = adj[j + 1], s2 = adj[j + 2], s3 = adj[j + 3];
        uint4 v0 = *(const uint4*)(g + (size_t)s0 * HID + col);
        uint4 v1 = *(const uint4*)(g + (size_t)s1 * HID + col);
        uint4 v2 = *(const uint4*)(g + (size_t)s2 * HID + col);
        uint4 v3 = *(const uint4*)(g + (size_t)s3 * HID + col);
        acc_add(acc, v0);
        acc_add(acc, v1);
        acc_add(acc, v2);
        acc_add(acc, v3);
    }
    for (; j < e1; j++) {
        int s = adj[j];
        uint4 v = *(const uint4*)(g + (size_t)s * HID + col);
        acc_add(acc, v);
    }
    float dv = dinv[node];
    float4 o0, o1;
    o0.x = fmaxf(fmaf(acc[0], dv, bias[col + 0]), 0.f);
    o0.y = fmaxf(fmaf(acc[1], dv, bias[col + 1]), 0.f);
    o0.z = fmaxf(fmaf(acc[2], dv, bias[col + 2]), 0.f);
    o0.w = fmaxf(fmaf(acc[3], dv, bias[col + 3]), 0.f);
    o1.x = fmaxf(fmaf(acc[4], dv, bias[col + 4]), 0.f);
    o1.y = fmaxf(fmaf(acc[5], dv, bias[col + 5]), 0.f);
    o1.z = fmaxf(fmaf(acc[6], dv, bias[col + 6]), 0.f);
    o1.w = fmaxf(fmaf(acc[7], dv, bias[col + 7]), 0.f);
    *(float4*)(h + (size_t)node * HID + col) = o0;
    *(float4*)(h + (size_t)node * HID + col + 4) = o1;
}

// ---------------- pooling partials ----------------
__global__ void pool_partial_k(const float* __restrict__ h, float* __restrict__ psum,
                               float* __restrict__ pmax) {
    int col = threadIdx.x;  // 256
    int b = blockIdx.x;     // PB
    float s = 0.0f, m = -1e30f;
    for (int r = b; r < NNODES; r += PB) {
        float v = h[(size_t)r * HID + col];
        s += v;
        m = fmaxf(m, v);
    }
    psum[b * HID + col] = s;
    pmax[b * HID + col] = m;
}

// ---------------- head ----------------
__global__ void head_k(const float* __restrict__ psum, const float* __restrict__ pmax,
                       const float* __restrict__ Wg1, const float* __restrict__ bg1,
                       const float* __restrict__ Wg2, const float* __restrict__ bg2,
                       const float* __restrict__ Wd1, const float* __restrict__ bd1,
                       const float* __restrict__ Wd2, const float* __restrict__ bd2,
                       float* __restrict__ out, float* __restrict__ prob) {
    __shared__ float rep[2 * HID];
    __shared__ float u1[HID];
    __shared__ float ge[EMB];
    __shared__ float v1[HID];
    __shared__ float vv[HID];
    __shared__ float red[HID];
    int t = threadIdx.x;  // 512

    if (t < HID) {
        float s = 0.0f;
        for (int i = 0; i < PB; i++) s += psum[i * HID + t];
        rep[t] = s * (1.0f / NNODES);
    } else {
        int c = t - HID;
        float m = -1e30f;
        for (int i = 0; i < PB; i++) m = fmaxf(m, pmax[i * HID + c]);
        rep[HID + c] = m;
    }
    __syncthreads();

    if (t < HID) {
        float s = bg1[t];
        for (int k = 0; k < 2 * HID; k++) s += rep[k] * Wg1[k * HID + t];
        u1[t] = fmaxf(s, 0.0f);
    }
    __syncthreads();

    if (t < EMB) {
        float s = bg2[t];
        for (int k = 0; k < HID; k++) s += u1[k] * Wg2[k * EMB + t];
        ge[t] = s;
        out[t] = s;
    }
    __syncthreads();

    if (t < HID) {
        float s = bd1[t];
        for (int k = 0; k < EMB; k++) s += ge[k] * Wd1[k * HID + t];
        v1[t] = fmaxf(s, 0.0f);
    }
    __syncthreads();

    if (t < HID) {
        float s = bd2[t];
        for (int k = 0; k < HID; k++) s += v1[k] * Wd2[k * HID + t];
        vv[t] = s;
    }
    __syncthreads();

    if (t < HID) red[t] = vv[t] * vv[t];
    __syncthreads();
    for (int s = HID / 2; s > 0; s >>= 1) {
        if (t < s) red[t] += red[t + s];
        __syncthreads();
    }
    if (t == 0) *prob = 1.0f / (1.0f + expf(-red[0]));
}

__global__ void fill_probs_k(float* __restrict__ out, const float* __restrict__ prob, int E) {
    int i = blockIdx.x * blockDim.x + threadIdx.x;
    float p = *prob;
    int base = i << 2;
    if (base + 3 < E) {
        *(float4*)(out + EMB + base) = make_float4(p, p, p, p);
    } else {
        for (int j = base; j < E; j++) out[EMB + j] = p;
    }
}

// ---------------- launch ----------------
extern "C" void kernel_launch(void* const* d_in, const int* in_sizes, int n_in,
                              void* d_out, int out_size) {
    const float* x = (const float*)d_in[0];
    const void* ei = d_in[1];
    const float* W1 = (const float*)d_in[2];
    const float* b1 = (const float*)d_in[3];
    const float* W2 = (const float*)d_in[4];
    const float* b2 = (const float*)d_in[5];
    const float* convW = (const float*)d_in[6];
    const float* convb = (const float*)d_in[7];
    const float* Wg1 = (const float*)d_in[8];
    const float* bg1 = (const float*)d_in[9];
    const float* Wg2 = (const float*)d_in[10];
    const float* bg2 = (const float*)d_in[11];
    const float* Wd1 = (const float*)d_in[12];
    const float* bd1 = (const float*)d_in[13];
    const float* Wd2 = (const float*)d_in[14];
    const float* bd2 = (const float*)d_in[15];

    int E = in_sizes[1] / 2;

    float *h, *t1, *dinv, *psum, *pmax, *prob;
    __half* gh;
    int *src, *dst, *cnt, *cursor, *off, *adj, *bsum, *flag;
    cudaGetSymbolAddress((void**)&h, g_h);
    cudaGetSymbolAddress((void**)&t1, g_t1);
    cudaGetSymbolAddress((void**)&gh, g_gh);
    cudaGetSymbolAddress((void**)&dinv, g_dinv);
    cudaGetSymbolAddress((void**)&psum, g_psum);
    cudaGetSymbolAddress((void**)&pmax, g_pmax);
    cudaGetSymbolAddress((void**)&prob, g_prob);
    cudaGetSymbolAddress((void**)&src, g_src);
    cudaGetSymbolAddress((void**)&dst, g_dst);
    cudaGetSymbolAddress((void**)&cnt, g_cnt);
    cudaGetSymbolAddress((void**)&cursor, g_cursor);
    cudaGetSymbolAddress((void**)&off, g_off);
    cudaGetSymbolAddress((void**)&adj, g_adj);
    cudaGetSymbolAddress((void**)&bsum, g_bsum);
    cudaGetSymbolAddress((void**)&flag, g_flag);

    cudaFuncSetAttribute(gemm_tf32_k, cudaFuncAttributeMaxDynamicSharedMemorySize, GEMM_SMEM);

    dim3 ggrid(NB_M, 2);
    set_flag_k<<<1, 1>>>(flag);                                                             // 0
    zero2_k<<<(NNODES + 255) / 256, 256>>>(cnt, cursor, NNODES);                            // 1
    detect_k<<<16, 256>>>((const int*)ei, flag);                                            // 2
    gemm_tf32_k<<<ggrid, 256, GEMM_SMEM>>>(x, W1, b1, t1, nullptr, nullptr, NNODES, 64, 1); // 3
    convert_edges_k<<<(E + 255) / 256, 256>>>(ei, flag, src, dst, cnt, E);                  // 4
    gemm_tf32_k<<<ggrid, 256, GEMM_SMEM>>>(t1, W2, b2, h, nullptr, nullptr, NNODES, HID, 0);// 5

    // CSR finish
    dinv_k<<<(NNODES + 255) / 256, 256>>>(cnt, dinv);
    scan1_k<<<SCAN_B, 256>>>(cnt, bsum);
    scan2_k<<<1, 32>>>(bsum);
    scan3_k<<<SCAN_B, 256>>>(cnt, bsum, off);
    fill_k<<<(E + 255) / 256, 256>>>(src, dst, off, cursor, adj, E);

    // GCN layers: gemm writes fp16 g (scaled by dinv); aggregate gathers fp16
    int agg_blocks = (NNODES * 32 + 255) / 256;
    for (int l = 0; l < 3; l++) {
        gemm_tf32_k<<<ggrid, 256, GEMM_SMEM>>>(h, convW + (size_t)l * HID * HID, nullptr,
                                               nullptr, gh, dinv, NNODES, HID, 0);
        aggregate_h_k<<<agg_blocks, 256>>>(off, adj, gh, dinv, convb + (size_t)l * HID, h);
    }

    // pooling + heads + output
    pool_partial_k<<<PB, 256>>>(h, psum, pmax);
    head_k<<<1, 512>>>(psum, pmax, Wg1, bg1, Wg2, bg2, Wd1, bd1, Wd2, bd2, (float*)d_out, prob);
    fill_probs_k<<<(E / 4 + 255) / 256, 256>>>((float*)d_out, prob, E);
}

// round 7
// speedup vs baseline: 4.7975x; 1.0153x over previous
#include <cuda_runtime.h>
#include <cuda_fp16.h>
#include <math.h>
#include <stdint.h>

#define NNODES 50000
#define HID 256
#define EMB 128
#define EMAX 800000
#define PB 120
#define NB_M 391   // ceil(50000/128)
#define SCAN_B 196 // ceil(50000/256)

// ---- scratch (static device globals: no allocation allowed) ----
__device__ float g_h[NNODES * HID];
__device__ float g_t1[NNODES * HID];
__device__ __half g_gh[NNODES * HID];
__device__ float g_dinv[NNODES];
__device__ float g_psum[PB * HID];
__device__ float g_pmax[PB * HID];
__device__ float g_prob;
__device__ int g_src[EMAX];
__device__ int g_dst[EMAX];
__device__ int g_cnt[NNODES];
__device__ int g_cursor[NNODES];
__device__ int g_off[NNODES + 1];
__device__ int g_adj[EMAX];
__device__ int g_bsum[SCAN_B];
__device__ int g_flag;

// ---------------- setup kernels (merged) ----------------
// init: flag=1, cnt/cursor zeroed
__global__ void init_k(int* flag, int* cnt, int* cursor) {
    int i = blockIdx.x * blockDim.x + threadIdx.x;
    if (i == 0) *flag = 1;
    if (i < NNODES) { cnt[i] = 0; cursor[i] = 0; }
}

// int64-vs-int32 sniff: int64 LE indices < 50000 have all odd words zero
__global__ void detect_k(const int* p, int* flag) {
    int i = blockIdx.x * blockDim.x + threadIdx.x;  // 4096 checks
    if (p[2 * i + 1] != 0) *flag = 0;
}

// convert + degree count fused
__global__ void convert_edges_k(const void* ei, const int* flag, int* src, int* dst,
                                int* cnt, int E) {
    int i = blockIdx.x * blockDim.x + threadIdx.x;
    if (i >= E) return;
    int s, d;
    if (*flag) {
        const long long* p = (const long long*)ei;
        s = (int)p[i];
        d = (int)p[E + i];
    } else {
        const int* p = (const int*)ei;
        s = p[i];
        d = p[E + i];
    }
    src[i] = s;
    dst[i] = d;
    atomicAdd(&cnt[d], 1);
}

// scanA: per-block sums of cnt -> bsum; also dinv
__global__ void scanA_k(const int* __restrict__ cnt, int* __restrict__ bsum,
                        float* __restrict__ dinv) {
    __shared__ int s[256];
    int t = threadIdx.x;
    int i = blockIdx.x * 256 + t;
    int v = (i < NNODES) ? cnt[i] : 0;
    if (i < NNODES) dinv[i] = rsqrtf((float)v + 1.0f);
    s[t] = v;
    __syncthreads();
    for (int d = 128; d > 0; d >>= 1) {
        if (t < d) s[t] += s[t + d];
        __syncthreads();
    }
    if (t == 0) bsum[blockIdx.x] = s[0];
}

// scanB: per-block base from bsum[0..b) + intra-block exclusive scan -> off
__global__ void scanB_k(const int* __restrict__ cnt, const int* __restrict__ bsum,
                        int* __restrict__ off) {
    __shared__ int s[256];
    __shared__ int red[256];
    int t = threadIdx.x;
    int b = blockIdx.x;
    int i = b * 256 + t;
    int val = (i < NNODES) ? cnt[i] : 0;

    // base = sum of bsum[j] for j < b
    int partial = 0;
    for (int j = t; j < b; j += 256) partial += bsum[j];
    red[t] = partial;
    __syncthreads();
    for (int d = 128; d > 0; d >>= 1) {
        if (t < d) red[t] += red[t + d];
        __syncthreads();
    }
    int base = red[0];

    // inclusive scan of val
    s[t] = val;
    __syncthreads();
    for (int d = 1; d < 256; d <<= 1) {
        int tmp = (t >= d) ? s[t - d] : 0;
        __syncthreads();
        s[t] += tmp;
        __syncthreads();
    }
    if (i <= NNODES) off[i] = base + s[t] - val;
}

__global__ void fill_k(const int* __restrict__ src, const int* __restrict__ dst,
                       const int* __restrict__ off, int* __restrict__ cursor,
                       int* __restrict__ adj, int E) {
    int i = blockIdx.x * blockDim.x + threadIdx.x;
    if (i >= E) return;
    int d = dst[i];
    int p = atomicAdd(&cursor[d], 1);
    adj[off[d] + p] = src[i];
}

// ---------------- TF32 tensor-core GEMM, 3-stage cp.async, 2 CTA/SM ----------------
// Block tile 128x128x32, 8 warps of 32x64, mma.m16n8k8.tf32.
// Output: fp32 C (encoder) or fp16 Ch (conv layers, pre-scaled by dinv).
#define AS_STRIDE 36
#define BS_STRIDE 136
#define STAGE_FLOATS (128 * AS_STRIDE + 32 * BS_STRIDE)  // 8960
#define GEMM_SMEM (3 * STAGE_FLOATS * 4)                 // 107520

__device__ __forceinline__ uint32_t tf32bits(float x) {
    uint32_t u;
    asm("cvt.rna.tf32.f32 %0, %1;" : "=r"(u) : "f"(x));
    return u;
}

__device__ __forceinline__ void cp_async16(float* smem_dst, const float* gsrc, bool pred) {
    uint32_t s = (uint32_t)__cvta_generic_to_shared(smem_dst);
    int sz = pred ? 16 : 0;
    asm volatile("cp.async.cg.shared.global [%0], [%1], 16, %2;\n"
                 :: "r"(s), "l"(gsrc), "r"(sz));
}

__global__ __launch_bounds__(256, 2) void gemm_tf32_k(
    const float* __restrict__ A, const float* __restrict__ B,
    const float* __restrict__ bias, float* __restrict__ C,
    __half* __restrict__ Ch, const float* __restrict__ dinvv,
    int M, int K, int relu_flag) {
    extern __shared__ float sm[];

    int tid = threadIdx.x;
    int warp = tid >> 5;
    int lane = tid & 31;
    int grp = lane >> 2;   // 0..7
    int tig = lane & 3;    // 0..3
    int wm = warp >> 1;    // 0..3 -> m offset wm*32
    int wn = warp & 1;     // 0..1 -> n offset wn*64
    int bm = blockIdx.x * 128;
    int bn = blockIdx.y * 128;
    int ntiles = K >> 5;

    float c[2][8][4];
#pragma unroll
    for (int mt = 0; mt < 2; mt++)
#pragma unroll
        for (int nt = 0; nt < 8; nt++)
#pragma unroll
            for (int q = 0; q < 4; q++) c[mt][nt][q] = 0.0f;

    auto stage = [&](int t, int buf) {
        float* As = sm + buf * STAGE_FLOATS;
        float* Bs = As + 128 * AS_STRIDE;
        int k0 = t << 5;
#pragma unroll
        for (int i = 0; i < 4; i++) {
            int ci = tid + i * 256;
            int row = ci >> 3;
            int col4 = (ci & 7) << 2;
            int gm = bm + row;
            bool ok = gm < M;
            int gms = ok ? gm : (M - 1);
            cp_async16(As + row * AS_STRIDE + col4, A + (size_t)gms * K + k0 + col4, ok);
        }
#pragma unroll
        for (int i = 0; i < 4; i++) {
            int ci = tid + i * 256;
            int row = ci >> 5;
            int col4 = (ci & 31) << 2;
            cp_async16(Bs + row * BS_STRIDE + col4,
                       B + (size_t)(k0 + row) * 256 + bn + col4, true);
        }
        asm volatile("cp.async.commit_group;\n");
    };

    stage(0, 0);
    if (ntiles > 1) stage(1, 1);

    for (int t = 0; t < ntiles; t++) {
        if (t + 2 < ntiles) stage(t + 2, (t + 2) % 3);
        int staged = (t + 3 < ntiles) ? (t + 3) : ntiles;
        int pend = staged - t - 1;
        if (pend >= 2) asm volatile("cp.async.wait_group 2;\n");
        else if (pend == 1) asm volatile("cp.async.wait_group 1;\n");
        else asm volatile("cp.async.wait_group 0;\n");
        __syncthreads();

        float* As = sm + (t % 3) * STAGE_FLOATS;
        float* Bs = As + 128 * AS_STRIDE;

#pragma unroll
        for (int ks = 0; ks < 4; ks++) {
            int kk = ks << 3;
            uint32_t af[2][4];
#pragma unroll
            for (int mt = 0; mt < 2; mt++) {
                int r0 = wm * 32 + mt * 16 + grp;
                af[mt][0] = tf32bits(As[r0 * AS_STRIDE + kk + tig]);
                af[mt][1] = tf32bits(As[(r0 + 8) * AS_STRIDE + kk + tig]);
                af[mt][2] = tf32bits(As[r0 * AS_STRIDE + kk + tig + 4]);
                af[mt][3] = tf32bits(As[(r0 + 8) * AS_STRIDE + kk + tig + 4]);
            }
#pragma unroll
            for (int nt = 0; nt < 8; nt++) {
                int col = wn * 64 + nt * 8 + grp;
                uint32_t b0 = tf32bits(Bs[(kk + tig) * BS_STRIDE + col]);
                uint32_t b1 = tf32bits(Bs[(kk + tig + 4) * BS_STRIDE + col]);
#pragma unroll
                for (int mt = 0; mt < 2; mt++) {
                    asm volatile(
                        "mma.sync.aligned.m16n8k8.row.col.f32.tf32.tf32.f32 "
                        "{%0,%1,%2,%3},{%4,%5,%6,%7},{%8,%9},{%0,%1,%2,%3};\n"
                        : "+f"(c[mt][nt][0]), "+f"(c[mt][nt][1]),
                          "+f"(c[mt][nt][2]), "+f"(c[mt][nt][3])
                        : "r"(af[mt][0]), "r"(af[mt][1]), "r"(af[mt][2]), "r"(af[mt][3]),
                          "r"(b0), "r"(b1));
                }
            }
        }
        __syncthreads();
    }

    // epilogue
#pragma unroll
    for (int mt = 0; mt < 2; mt++) {
        int r0 = bm + wm * 32 + mt * 16 + grp;
        int r1 = r0 + 8;
        float d0 = 1.0f, d1 = 1.0f;
        if (dinvv) {
            if (r0 < M) d0 = dinvv[r0];
            if (r1 < M) d1 = dinvv[r1];
        }
#pragma unroll
        for (int nt = 0; nt < 8; nt++) {
            int col = bn + wn * 64 + nt * 8 + 2 * tig;
            float b0f = 0.f, b1f = 0.f;
            if (bias) { b0f = bias[col]; b1f = bias[col + 1]; }
            float v0 = c[mt][nt][0] + b0f;
            float v1 = c[mt][nt][1] + b1f;
            float v2 = c[mt][nt][2] + b0f;
            float v3 = c[mt][nt][3] + b1f;
            if (relu_flag) {
                v0 = fmaxf(v0, 0.f); v1 = fmaxf(v1, 0.f);
                v2 = fmaxf(v2, 0.f); v3 = fmaxf(v3, 0.f);
            }
            v0 *= d0; v1 *= d0; v2 *= d1; v3 *= d1;
            if (Ch) {
                if (r0 < M) *(__half2*)(Ch + (size_t)r0 * 256 + col) = __floats2half2_rn(v0, v1);
                if (r1 < M) *(__half2*)(Ch + (size_t)r1 * 256 + col) = __floats2half2_rn(v2, v3);
            } else {
                if (r0 < M) *(float2*)(C + (size_t)r0 * 256 + col) = make_float2(v0, v1);
                if (r1 < M) *(float2*)(C + (size_t)r1 * 256 + col) = make_float2(v2, v3);
            }
        }
    }
}

// ---------------- CSR aggregate (fp16 gather, 4-way unrolled) ----------------
__device__ __forceinline__ void acc_add(float* acc, uint4 v) {
    const __half2* p = (const __half2*)&v;
#pragma unroll
    for (int q = 0; q < 4; q++) {
        float2 f = __half22float2(p[q]);
        acc[2 * q] += f.x;
        acc[2 * q + 1] += f.y;
    }
}

__global__ void aggregate_h_k(const int* __restrict__ off, const int* __restrict__ adj,
                              const __half* __restrict__ g, const float* __restrict__ dinv,
                              const float* __restrict__ bias, float* __restrict__ h) {
    int node = (blockIdx.x * blockDim.x + threadIdx.x) >> 5;
    if (node >= NNODES) return;
    int lane = threadIdx.x & 31;
    int col = lane << 3;  // 8 halves per lane

    float acc[8];
    {
        uint4 v = *(const uint4*)(g + (size_t)node * HID + col);  // self loop
        const __half2* p = (const __half2*)&v;
#pragma unroll
        for (int q = 0; q < 4; q++) {
            float2 f = __half22float2(p[q]);
            acc[2 * q] = f.x;
            acc[2 * q + 1] = f.y;
        }
    }
    int e0 = off[node], e1 = off[node + 1];
    int j = e0;
    for (; j + 4 <= e1; j += 4) {
        int s0 = adj[j], s1 = adj[j + 1], s2 = adj[j + 2], s3 = adj[j + 3];
        uint4 v0 = *(const uint4*)(g + (size_t)s0 * HID + col);
        uint4 v1 = *(const uint4*)(g + (size_t)s1 * HID + col);
        uint4 v2 = *(const uint4*)(g + (size_t)s2 * HID + col);
        uint4 v3 = *(const uint4*)(g + (size_t)s3 * HID + col);
        acc_add(acc, v0);
        acc_add(acc, v1);
        acc_add(acc, v2);
        acc_add(acc, v3);
    }
    for (; j < e1; j++) {
        int s = adj[j];
        uint4 v = *(const uint4*)(g + (size_t)s * HID + col);
        acc_add(acc, v);
    }
    float dv = dinv[node];
    float4 o0, o1;
    o0.x = fmaxf(fmaf(acc[0], dv, bias[col + 0]), 0.f);
    o0.y = fmaxf(fmaf(acc[1], dv, bias[col + 1]), 0.f);
    o0.z = fmaxf(fmaf(acc[2], dv, bias[col + 2]), 0.f);
    o0.w = fmaxf(fmaf(acc[3], dv, bias[col + 3]), 0.f);
    o1.x = fmaxf(fmaf(acc[4], dv, bias[col + 4]), 0.f);
    o1.y = fmaxf(fmaf(acc[5], dv, bias[col + 5]), 0.f);
    o1.z = fmaxf(fmaf(acc[6], dv, bias[col + 6]), 0.f);
    o1.w = fmaxf(fmaf(acc[7], dv, bias[col + 7]), 0.f);
    *(float4*)(h + (size_t)node * HID + col) = o0;
    *(float4*)(h + (size_t)node * HID + col + 4) = o1;
}

// ---------------- pooling partials ----------------
__global__ void pool_partial_k(const float* __restrict__ h, float* __restrict__ psum,
                               float* __restrict__ pmax) {
    int col = threadIdx.x;  // 256
    int b = blockIdx.x;     // PB
    float s = 0.0f, m = -1e30f;
    for (int r = b; r < NNODES; r += PB) {
        float v = h[(size_t)r * HID + col];
        s += v;
        m = fmaxf(m, v);
    }
    psum[b * HID + col] = s;
    pmax[b * HID + col] = m;
}

// ---------------- head ----------------
__global__ void head_k(const float* __restrict__ psum, const float* __restrict__ pmax,
                       const float* __restrict__ Wg1, const float* __restrict__ bg1,
                       const float* __restrict__ Wg2, const float* __restrict__ bg2,
                       const float* __restrict__ Wd1, const float* __restrict__ bd1,
                       const float* __restrict__ Wd2, const float* __restrict__ bd2,
                       float* __restrict__ out, float* __restrict__ prob) {
    __shared__ float rep[2 * HID];
    __shared__ float u1[HID];
    __shared__ float ge[EMB];
    __shared__ float v1[HID];
    __shared__ float vv[HID];
    __shared__ float red[HID];
    int t = threadIdx.x;  // 512

    if (t < HID) {
        float s = 0.0f;
        for (int i = 0; i < PB; i++) s += psum[i * HID + t];
        rep[t] = s * (1.0f / NNODES);
    } else {
        int c = t - HID;
        float m = -1e30f;
        for (int i = 0; i < PB; i++) m = fmaxf(m, pmax[i * HID + c]);
        rep[HID + c] = m;
    }
    __syncthreads();

    if (t < HID) {
        float s = bg1[t];
        for (int k = 0; k < 2 * HID; k++) s += rep[k] * Wg1[k * HID + t];
        u1[t] = fmaxf(s, 0.0f);
    }
    __syncthreads();

    if (t < EMB) {
        float s = bg2[t];
        for (int k = 0; k < HID; k++) s += u1[k] * Wg2[k * EMB + t];
        ge[t] = s;
        out[t] = s;
    }
    __syncthreads();

    if (t < HID) {
        float s = bd1[t];
        for (int k = 0; k < EMB; k++) s += ge[k] * Wd1[k * HID + t];
        v1[t] = fmaxf(s, 0.0f);
    }
    __syncthreads();

    if (t < HID) {
        float s = bd2[t];
        for (int k = 0; k < HID; k++) s += v1[k] * Wd2[k * HID + t];
        vv[t] = s;
    }
    __syncthreads();

    if (t < HID) red[t] = vv[t] * vv[t];
    __syncthreads();
    for (int s = HID / 2; s > 0; s >>= 1) {
        if (t < s) red[t] += red[t + s];
        __syncthreads();
    }
    if (t == 0) *prob = 1.0f / (1.0f + expf(-red[0]));
}

__global__ void fill_probs_k(float* __restrict__ out, const float* __restrict__ prob, int E) {
    int i = blockIdx.x * blockDim.x + threadIdx.x;
    float p = *prob;
    int base = i << 2;
    if (base + 3 < E) {
        *(float4*)(out + EMB + base) = make_float4(p, p, p, p);
    } else {
        for (int j = base; j < E; j++) out[EMB + j] = p;
    }
}

// ---------------- launch ----------------
extern "C" void kernel_launch(void* const* d_in, const int* in_sizes, int n_in,
                              void* d_out, int out_size) {
    const float* x = (const float*)d_in[0];
    const void* ei = d_in[1];
    const float* W1 = (const float*)d_in[2];
    const float* b1 = (const float*)d_in[3];
    const float* W2 = (const float*)d_in[4];
    const float* b2 = (const float*)d_in[5];
    const float* convW = (const float*)d_in[6];
    const float* convb = (const float*)d_in[7];
    const float* Wg1 = (const float*)d_in[8];
    const float* bg1 = (const float*)d_in[9];
    const float* Wg2 = (const float*)d_in[10];
    const float* bg2 = (const float*)d_in[11];
    const float* Wd1 = (const float*)d_in[12];
    const float* bd1 = (const float*)d_in[13];
    const float* Wd2 = (const float*)d_in[14];
    const float* bd2 = (const float*)d_in[15];

    int E = in_sizes[1] / 2;

    float *h, *t1, *dinv, *psum, *pmax, *prob;
    __half* gh;
    int *src, *dst, *cnt, *cursor, *off, *adj, *bsum, *flag;
    cudaGetSymbolAddress((void**)&h, g_h);
    cudaGetSymbolAddress((void**)&t1, g_t1);
    cudaGetSymbolAddress((void**)&gh, g_gh);
    cudaGetSymbolAddress((void**)&dinv, g_dinv);
    cudaGetSymbolAddress((void**)&psum, g_psum);
    cudaGetSymbolAddress((void**)&pmax, g_pmax);
    cudaGetSymbolAddress((void**)&prob, g_prob);
    cudaGetSymbolAddress((void**)&src, g_src);
    cudaGetSymbolAddress((void**)&dst, g_dst);
    cudaGetSymbolAddress((void**)&cnt, g_cnt);
    cudaGetSymbolAddress((void**)&cursor, g_cursor);
    cudaGetSymbolAddress((void**)&off, g_off);
    cudaGetSymbolAddress((void**)&adj, g_adj);
    cudaGetSymbolAddress((void**)&bsum, g_bsum);
    cudaGetSymbolAddress((void**)&flag, g_flag);

    cudaFuncSetAttribute(gemm_tf32_k, cudaFuncAttributeMaxDynamicSharedMemorySize, GEMM_SMEM);

    dim3 ggrid(NB_M, 2);
    // CSR build first; slot 5 = fill_k for ncu evidence
    init_k<<<(NNODES + 255) / 256, 256>>>(flag, cnt, cursor);               // 0
    detect_k<<<16, 256>>>((const int*)ei, flag);                            // 1
    convert_edges_k<<<(E + 255) / 256, 256>>>(ei, flag, src, dst, cnt, E);  // 2
    scanA_k<<<SCAN_B, 256>>>(cnt, bsum, dinv);                              // 3
    scanB_k<<<SCAN_B, 256>>>(cnt, bsum, off);                               // 4
    fill_k<<<(E + 255) / 256, 256>>>(src, dst, off, cursor, adj, E);        // 5 <- ncu

    // node encoder
    gemm_tf32_k<<<ggrid, 256, GEMM_SMEM>>>(x, W1, b1, t1, nullptr, nullptr, NNODES, 64, 1);
    gemm_tf32_k<<<ggrid, 256, GEMM_SMEM>>>(t1, W2, b2, h, nullptr, nullptr, NNODES, HID, 0);

    // GCN layers
    int agg_blocks = (NNODES * 32 + 255) / 256;
    for (int l = 0; l < 3; l++) {
        gemm_tf32_k<<<ggrid, 256, GEMM_SMEM>>>(h, convW + (size_t)l * HID * HID, nullptr,
                                               nullptr, gh, dinv, NNODES, HID, 0);
        aggregate_h_k<<<agg_blocks, 256>>>(off, adj, gh, dinv, convb + (size_t)l * HID, h);
    }

    // pooling + heads + output
    pool_partial_k<<<PB, 256>>>(h, psum, pmax);
    head_k<<<1, 512>>>(psum, pmax, Wg1, bg1, Wg2, bg2, Wd1, bd1, Wd2, bd2, (float*)d_out, prob);
    fill_probs_k<<<(E / 4 + 255) / 256, 256>>>((float*)d_out, prob, E);
}

// round 9
// speedup vs baseline: 6.7503x; 1.4070x over previous
#include <cuda_runtime.h>
#include <cuda_fp16.h>
#include <math.h>
#include <stdint.h>

#define NNODES 50000
#define HID 256
#define EMB 128
#define FIN 64
#define EMAX 800000
#define PB 120
#define SCAN_B 196
#define NB_M 391  // ceil(50000/128)

#define XN (NNODES * FIN)
#define WT2_OFF 16384
#define WTC_OFF (16384 + 65536)
#define WT_TOTAL (WTC_OFF + 3 * 65536)

// ---- scratch (static device globals: no allocation allowed) ----
__device__ __half g_hh[NNODES * HID];   // node features (fp16)
__device__ __half g_t1[NNODES * HID];   // encoder intermediate
__device__ __half g_gh[NNODES * HID];   // per-layer g = dinv*(h@W)
__device__ __half g_xh[XN];             // x in fp16
__device__ __half g_wt[WT_TOTAL];       // transposed fp16 weights [N][K]
__device__ float g_dinv[NNODES];
__device__ float g_psum[PB * HID];
__device__ float g_pmax[PB * HID];
__device__ float g_prob;
__device__ int g_src[EMAX];
__device__ int g_dst[EMAX];
__device__ int g_cnt[NNODES];
__device__ int g_cursor[NNODES];
__device__ int g_off[NNODES + 1];
__device__ int g_adj[EMAX];
__device__ int g_bsum[SCAN_B];
__device__ int g_flag;

// ---------------- helpers ----------------
__device__ __forceinline__ uint32_t smem_u32(const void* p) {
    uint32_t a;
    asm("{ .reg .u64 t; cvta.to.shared.u64 t, %1; cvt.u32.u64 %0, t; }" : "=r"(a) : "l"(p));
    return a;
}

__device__ __forceinline__ void cp_async16(void* smem_dst, const void* gsrc, bool pred) {
    uint32_t s = (uint32_t)__cvta_generic_to_shared(smem_dst);
    int sz = pred ? 16 : 0;
    asm volatile("cp.async.cg.shared.global [%0], [%1], 16, %2;\n" :: "r"(s), "l"(gsrc), "r"(sz));
}

__device__ __forceinline__ void ldm_x4(uint32_t& r0, uint32_t& r1, uint32_t& r2, uint32_t& r3,
                                       uint32_t addr) {
    asm volatile("ldmatrix.sync.aligned.m8n8.x4.shared.b16 {%0,%1,%2,%3}, [%4];"
                 : "=r"(r0), "=r"(r1), "=r"(r2), "=r"(r3) : "r"(addr));
}

// ---------------- setup kernels ----------------
__global__ void init_k(int* flag, int* cnt, int* cursor) {
    int i = blockIdx.x * blockDim.x + threadIdx.x;
    if (i == 0) *flag = 1;
    if (i < NNODES) { cnt[i] = 0; cursor[i] = 0; }
}

// prep: xh = fp16(x); wt = fp16(transpose(W1,W2,convW)) into [N,K] K-major
__global__ void prep_k(const float* __restrict__ x, const float* __restrict__ W1,
                       const float* __restrict__ W2, const float* __restrict__ convW,
                       __half* __restrict__ xh, __half* __restrict__ wt) {
    int i = blockIdx.x * blockDim.x + threadIdx.x;
    if (i < XN) { xh[i] = __float2half_rn(x[i]); return; }
    int j = i - XN;
    if (j < 16384) {  // Wt1[n][k], k<64
        int n = j >> 6, k = j & 63;
        wt[j] = __float2half_rn(W1[k * 256 + n]);
        return;
    }
    j -= 16384;
    if (j < 65536) {  // Wt2[n][k]
        int n = j >> 8, k = j & 255;
        wt[WT2_OFF + j] = __float2half_rn(W2[k * 256 + n]);
        return;
    }
    j -= 65536;
    if (j < 3 * 65536) {
        int l = j >> 16;
        int r = j & 65535;
        int n = r >> 8, k = r & 255;
        wt[WTC_OFF + j] = __float2half_rn(convW[l * 65536 + k * 256 + n]);
    }
}

__global__ void detect_k(const int* p, int* flag) {
    int i = blockIdx.x * blockDim.x + threadIdx.x;
    if (p[2 * i + 1] != 0) *flag = 0;
}

__global__ void convert_edges_k(const void* ei, const int* flag, int* src, int* dst,
                                int* cnt, int E) {
    int i = blockIdx.x * blockDim.x + threadIdx.x;
    if (i >= E) return;
    int s, d;
    if (*flag) {
        const long long* p = (const long long*)ei;
        s = (int)p[i];
        d = (int)p[E + i];
    } else {
        const int* p = (const int*)ei;
        s = p[i];
        d = p[E + i];
    }
    src[i] = s;
    dst[i] = d;
    atomicAdd(&cnt[d], 1);
}

__global__ void scanA_k(const int* __restrict__ cnt, int* __restrict__ bsum,
                        float* __restrict__ dinv) {
    __shared__ int s[256];
    int t = threadIdx.x;
    int i = blockIdx.x * 256 + t;
    int v = (i < NNODES) ? cnt[i] : 0;
    if (i < NNODES) dinv[i] = rsqrtf((float)v + 1.0f);
    s[t] = v;
    __syncthreads();
    for (int d = 128; d > 0; d >>= 1) {
        if (t < d) s[t] += s[t + d];
        __syncthreads();
    }
    if (t == 0) bsum[blockIdx.x] = s[0];
}

__global__ void scanB_k(const int* __restrict__ cnt, const int* __restrict__ bsum,
                        int* __restrict__ off) {
    __shared__ int s[256];
    __shared__ int red[256];
    int t = threadIdx.x;
    int b = blockIdx.x;
    int i = b * 256 + t;
    int val = (i < NNODES) ? cnt[i] : 0;
    int partial = 0;
    for (int j = t; j < b; j += 256) partial += bsum[j];
    red[t] = partial;
    __syncthreads();
    for (int d = 128; d > 0; d >>= 1) {
        if (t < d) red[t] += red[t + d];
        __syncthreads();
    }
    int base = red[0];
    s[t] = val;
    __syncthreads();
    for (int d = 1; d < 256; d <<= 1) {
        int tmp = (t >= d) ? s[t - d] : 0;
        __syncthreads();
        s[t] += tmp;
        __syncthreads();
    }
    if (i <= NNODES) off[i] = base + s[t] - val;
}

__global__ void fill_k(const int* __restrict__ src, const int* __restrict__ dst,
                       const int* __restrict__ off, int* __restrict__ cursor,
                       int* __restrict__ adj, int E) {
    int i = blockIdx.x * blockDim.x + threadIdx.x;
    if (i >= E) return;
    int d = dst[i];
    int p = atomicAdd(&cursor[d], 1);
    adj[off[d] + p] = src[i];
}

// ---------------- FP16 tensor-core GEMM (mma.m16n8k16 + ldmatrix) ----------------
// C[M,256] slice: CTA computes rows [bm,bm+128) x cols [bn,bn+128).
// A [M,K] fp16 row-major; Bt [256,K] fp16 (pre-transposed). BK=64 (128B rows, SW128).
// 8 warps: warp (wm 0..3, wn 0..1) owns 32x64. 3-stage cp.async pipeline, 2 CTA/SM.
#define TILE_BYTES 16384                 // 128 x 128B
#define STAGE_BYTES (2 * TILE_BYTES)     // A + B
#define NSTAGE 3
#define GEMM_SMEM (NSTAGE * STAGE_BYTES) // 98304

__global__ __launch_bounds__(256, 2) void gemm_h_k(
    const __half* __restrict__ A, const __half* __restrict__ Bt,
    const float* __restrict__ bias, __half* __restrict__ Cout,
    const float* __restrict__ dinvv, int M, int K, int relu_flag) {
    extern __shared__ char smem[];
    uint32_t sb = smem_u32(smem);

    int tid = threadIdx.x;
    int warp = tid >> 5;
    int lane = tid & 31;
    int grp = lane >> 2;   // 0..7
    int tig = lane & 3;    // 0..3
    int wm = warp >> 1;    // 0..3 -> m offset wm*32
    int wn = warp & 1;     // 0..1 -> n offset wn*64
    int bm = blockIdx.x * 128;
    int bn = blockIdx.y * 128;
    int ntiles = K >> 6;

    float c[2][8][4];
#pragma unroll
    for (int mt = 0; mt < 2; mt++)
#pragma unroll
        for (int nt = 0; nt < 8; nt++)
#pragma unroll
            for (int q = 0; q < 4; q++) c[mt][nt][q] = 0.0f;

    // stage tile t: A rows [bm,bm+128) k [t*64,(t+1)*64); B rows [bn,bn+128) same k.
    // SW128 swizzle: 16B-chunk c at row r stored at chunk (c ^ (r&7)).
    auto stage = [&](int t) {
        char* As = smem + (t % NSTAGE) * STAGE_BYTES;
        char* Bs = As + TILE_BYTES;
        int k0 = t << 6;
#pragma unroll
        for (int i = 0; i < 4; i++) {
            int ci = tid + i * 256;   // 0..1023
            int row = ci >> 3;
            int ch = ci & 7;
            uint32_t sw = (uint32_t)(row * 128 + ((ch ^ (row & 7)) << 4));
            int gm = bm + row;
            bool ok = gm < M;
            int gms = ok ? gm : 0;
            cp_async16(As + sw, A + (size_t)gms * K + k0 + ch * 8, ok);
            cp_async16(Bs + sw, Bt + (size_t)(bn + row) * K + k0 + ch * 8, true);
        }
        asm volatile("cp.async.commit_group;\n");
    };

    stage(0);
    if (ntiles > 1) stage(1);

    for (int t = 0; t < ntiles; t++) {
        if (t + 2 < ntiles) stage(t + 2);
        int staged3 = (t + 3 < ntiles) ? (t + 3) : ntiles;
        int pend = staged3 - t - 1;
        if (pend >= 2) asm volatile("cp.async.wait_group 2;\n");
        else if (pend == 1) asm volatile("cp.async.wait_group 1;\n");
        else asm volatile("cp.async.wait_group 0;\n");
        __syncthreads();

        uint32_t as_b = sb + (t % NSTAGE) * STAGE_BYTES;
        uint32_t bs_b = as_b + TILE_BYTES;

#pragma unroll
        for (int ks = 0; ks < 4; ks++) {
            int kc0 = ks << 1;  // 16B-chunk index of this k16 step
            // A fragments: x4 -> a0..a3 (m0-7/klo, m8-15/klo, m0-7/khi, m8-15/khi)
            uint32_t a[2][4];
#pragma unroll
            for (int mt = 0; mt < 2; mt++) {
                int row = wm * 32 + mt * 16 + (lane & 7) + (lane & 8);
                int ch = kc0 + (lane >> 4);
                uint32_t addr = as_b + (uint32_t)(row * 128 + ((ch ^ (row & 7)) << 4));
                ldm_x4(a[mt][0], a[mt][1], a[mt][2], a[mt][3], addr);
            }
            // B fragments: per x4 -> (n0-7/klo, n0-7/khi, n8-15/klo, n8-15/khi)
            uint32_t b[8][2];
#pragma unroll
            for (int p = 0; p < 4; p++) {
                int nrow = wn * 64 + p * 16 + (lane & 7) + ((lane & 16) >> 1);
                int ch = kc0 + ((lane >> 3) & 1);
                uint32_t addr = bs_b + (uint32_t)(nrow * 128 + ((ch ^ (nrow & 7)) << 4));
                uint32_t r0, r1, r2, r3;
                ldm_x4(r0, r1, r2, r3, addr);
                b[2 * p][0] = r0; b[2 * p][1] = r1;
                b[2 * p + 1][0] = r2; b[2 * p + 1][1] = r3;
            }
#pragma unroll
            for (int mt = 0; mt < 2; mt++)
#pragma unroll
                for (int nt = 0; nt < 8; nt++) {
                    asm volatile(
                        "mma.sync.aligned.m16n8k16.row.col.f32.f16.f16.f32 "
                        "{%0,%1,%2,%3},{%4,%5,%6,%7},{%8,%9},{%0,%1,%2,%3};\n"
                        : "+f"(c[mt][nt][0]), "+f"(c[mt][nt][1]),
                          "+f"(c[mt][nt][2]), "+f"(c[mt][nt][3])
                        : "r"(a[mt][0]), "r"(a[mt][1]), "r"(a[mt][2]), "r"(a[mt][3]),
                          "r"(b[nt][0]), "r"(b[nt][1]));
                }
        }
        __syncthreads();
    }

    // epilogue: C frag rows grp, grp+8; cols 2*tig, 2*tig+1 within each (mt,nt) 16x8 tile
#pragma unroll
    for (int mt = 0; mt < 2; mt++) {
        int r0 = bm + wm * 32 + mt * 16 + grp;
        int r1 = r0 + 8;
        float d0 = 1.0f, d1 = 1.0f;
        if (dinvv) {
            if (r0 < M) d0 = dinvv[r0];
            if (r1 < M) d1 = dinvv[r1];
        }
#pragma unroll
        for (int nt = 0; nt < 8; nt++) {
            int col = bn + wn * 64 + nt * 8 + 2 * tig;
            float b0f = 0.f, b1f = 0.f;
            if (bias) { b0f = bias[col]; b1f = bias[col + 1]; }
            float v0 = c[mt][nt][0] + b0f;
            float v1 = c[mt][nt][1] + b1f;
            float v2 = c[mt][nt][2] + b0f;
            float v3 = c[mt][nt][3] + b1f;
            if (relu_flag) {
                v0 = fmaxf(v0, 0.f); v1 = fmaxf(v1, 0.f);
                v2 = fmaxf(v2, 0.f); v3 = fmaxf(v3, 0.f);
            }
            v0 *= d0; v1 *= d0; v2 *= d1; v3 *= d1;
            if (r0 < M) *(__half2*)(Cout + (size_t)r0 * 256 + col) = __floats2half2_rn(v0, v1);
            if (r1 < M) *(__half2*)(Cout + (size_t)r1 * 256 + col) = __floats2half2_rn(v2, v3);
        }
    }
}

// ---------------- CSR aggregate (fp16 gather, 4-way unrolled, fp16 h output) ----------------
__device__ __forceinline__ void acc_add(float* acc, uint4 v) {
    const __half2* p = (const __half2*)&v;
#pragma unroll
    for (int q = 0; q < 4; q++) {
        float2 f = __half22float2(p[q]);
        acc[2 * q] += f.x;
        acc[2 * q + 1] += f.y;
    }
}

__global__ void aggregate_h_k(const int* __restrict__ off, const int* __restrict__ adj,
                              const __half* __restrict__ g, const float* __restrict__ dinv,
                              const float* __restrict__ bias, __half* __restrict__ h) {
    int node = (blockIdx.x * blockDim.x + threadIdx.x) >> 5;
    if (node >= NNODES) return;
    int lane = threadIdx.x & 31;
    int col = lane << 3;

    float acc[8];
    {
        uint4 v = *(const uint4*)(g + (size_t)node * HID + col);
        const __half2* p = (const __half2*)&v;
#pragma unroll
        for (int q = 0; q < 4; q++) {
            float2 f = __half22float2(p[q]);
            acc[2 * q] = f.x;
            acc[2 * q + 1] = f.y;
        }
    }
    int e0 = off[node], e1 = off[node + 1];
    int j = e0;
    for (; j + 4 <= e1; j += 4) {
        int s0 = adj[j], s1 = adj[j + 1], s2 = adj[j + 2], s3 = adj[j + 3];
        uint4 v0 = *(const uint4*)(g + (size_t)s0 * HID + col);
        uint4 v1 = *(const uint4*)(g + (size_t)s1 * HID + col);
        uint4 v2 = *(const uint4*)(g + (size_t)s2 * HID + col);
        uint4 v3 = *(const uint4*)(g + (size_t)s3 * HID + col);
        acc_add(acc, v0);
        acc_add(acc, v1);
        acc_add(acc, v2);
        acc_add(acc, v3);
    }
    for (; j < e1; j++) {
        int s = adj[j];
        uint4 v = *(const uint4*)(g + (size_t)s * HID + col);
        acc_add(acc, v);
    }
    float dvv = dinv[node];
    uint32_t hp[4];
#pragma unroll
    for (int q = 0; q < 4; q++) {
        float o0 = fmaxf(fmaf(acc[2 * q], dvv, bias[col + 2 * q]), 0.0f);
        float o1 = fmaxf(fmaf(acc[2 * q + 1], dvv, bias[col + 2 * q + 1]), 0.0f);
        __half2 h2 = __floats2half2_rn(o0, o1);
        hp[q] = *(uint32_t*)&h2;
    }
    *(uint4*)(h + (size_t)node * HID + col) = make_uint4(hp[0], hp[1], hp[2], hp[3]);
}

// ---------------- pooling + head + output ----------------
__global__ void pool_partial_k(const __half* __restrict__ h, float* __restrict__ psum,
                               float* __restrict__ pmax) {
    int col = threadIdx.x;
    int b = blockIdx.x;
    float s = 0.0f, m = -1e30f;
    for (int r = b; r < NNODES; r += PB) {
        float v = __half2float(h[(size_t)r * HID + col]);
        s += v;
        m = fmaxf(m, v);
    }
    psum[b * HID + col] = s;
    pmax[b * HID + col] = m;
}

__global__ void head_k(const float* __restrict__ psum, const float* __restrict__ pmax,
                       const float* __restrict__ Wg1, const float* __restrict__ bg1,
                       const float* __restrict__ Wg2, const float* __restrict__ bg2,
                       const float* __restrict__ Wd1, const float* __restrict__ bd1,
                       const float* __restrict__ Wd2, const float* __restrict__ bd2,
                       float* __restrict__ out, float* __restrict__ prob) {
    __shared__ float rep[2 * HID];
    __shared__ float u1[HID];
    __shared__ float ge[EMB];
    __shared__ float v1[HID];
    __shared__ float vv[HID];
    __shared__ float red[HID];
    int t = threadIdx.x;

    if (t < HID) {
        float s = 0.0f;
        for (int i = 0; i < PB; i++) s += psum[i * HID + t];
        rep[t] = s * (1.0f / NNODES);
    } else {
        int c = t - HID;
        float m = -1e30f;
        for (int i = 0; i < PB; i++) m = fmaxf(m, pmax[i * HID + c]);
        rep[HID + c] = m;
    }
    __syncthreads();

    if (t < HID) {
        float s = bg1[t];
        for (int k = 0; k < 2 * HID; k++) s += rep[k] * Wg1[k * HID + t];
        u1[t] = fmaxf(s, 0.0f);
    }
    __syncthreads();

    if (t < EMB) {
        float s = bg2[t];
        for (int k = 0; k < HID; k++) s += u1[k] * Wg2[k * EMB + t];
        ge[t] = s;
        out[t] = s;
    }
    __syncthreads();

    if (t < HID) {
        float s = bd1[t];
        for (int k = 0; k < EMB; k++) s += ge[k] * Wd1[k * HID + t];
        v1[t] = fmaxf(s, 0.0f);
    }
    __syncthreads();

    if (t < HID) {
        float s = bd2[t];
        for (int k = 0; k < HID; k++) s += v1[k] * Wd2[k * HID + t];
        vv[t] = s;
    }
    __syncthreads();

    if (t < HID) red[t] = vv[t] * vv[t];
    __syncthreads();
    for (int s = HID / 2; s > 0; s >>= 1) {
        if (t < s) red[t] += red[t + s];
        __syncthreads();
    }
    if (t == 0) *prob = 1.0f / (1.0f + expf(-red[0]));
}

__global__ void fill_probs_k(float* __restrict__ out, const float* __restrict__ prob, int E) {
    int i = blockIdx.x * blockDim.x + threadIdx.x;
    float p = *prob;
    int base = i << 2;
    if (base + 3 < E) {
        *(float4*)(out + EMB + base) = make_float4(p, p, p, p);
    } else {
        for (int j = base; j < E; j++) out[EMB + j] = p;
    }
}

// ---------------- launch ----------------
extern "C" void kernel_launch(void* const* d_in, const int* in_sizes, int n_in,
                              void* d_out, int out_size) {
    const float* x = (const float*)d_in[0];
    const void* ei = d_in[1];
    const float* W1 = (const float*)d_in[2];
    const float* b1 = (const float*)d_in[3];
    const float* W2 = (const float*)d_in[4];
    const float* b2 = (const float*)d_in[5];
    const float* convW = (const float*)d_in[6];
    const float* convb = (const float*)d_in[7];
    const float* Wg1 = (const float*)d_in[8];
    const float* bg1 = (const float*)d_in[9];
    const float* Wg2 = (const float*)d_in[10];
    const float* bg2 = (const float*)d_in[11];
    const float* Wd1 = (const float*)d_in[12];
    const float* bd1 = (const float*)d_in[13];
    const float* Wd2 = (const float*)d_in[14];
    const float* bd2 = (const float*)d_in[15];

    int E = in_sizes[1] / 2;

    float *dinv, *psum, *pmax, *prob;
    __half *hh, *t1, *gh, *xh, *wt;
    int *src, *dst, *cnt, *cursor, *off, *adj, *bsum, *flag;
    cudaGetSymbolAddress((void**)&hh, g_hh);
    cudaGetSymbolAddress((void**)&t1, g_t1);
    cudaGetSymbolAddress((void**)&gh, g_gh);
    cudaGetSymbolAddress((void**)&xh, g_xh);
    cudaGetSymbolAddress((void**)&wt, g_wt);
    cudaGetSymbolAddress((void**)&dinv, g_dinv);
    cudaGetSymbolAddress((void**)&psum, g_psum);
    cudaGetSymbolAddress((void**)&pmax, g_pmax);
    cudaGetSymbolAddress((void**)&prob, g_prob);
    cudaGetSymbolAddress((void**)&src, g_src);
    cudaGetSymbolAddress((void**)&dst, g_dst);
    cudaGetSymbolAddress((void**)&cnt, g_cnt);
    cudaGetSymbolAddress((void**)&cursor, g_cursor);
    cudaGetSymbolAddress((void**)&off, g_off);
    cudaGetSymbolAddress((void**)&adj, g_adj);
    cudaGetSymbolAddress((void**)&bsum, g_bsum);
    cudaGetSymbolAddress((void**)&flag, g_flag);

    cudaFuncSetAttribute(gemm_h_k, cudaFuncAttributeMaxDynamicSharedMemorySize, GEMM_SMEM);

    dim3 ggrid(NB_M, 2);  // 128x128 tiles over [50000, 256]
    int prep_blocks = (XN + WT_TOTAL + 255) / 256;

    // slot 3 = K=256 fp16 GEMM (ncu probe)
    prep_k<<<prep_blocks, 256>>>(x, W1, W2, convW, xh, wt);                          // 0
    init_k<<<(NNODES + 255) / 256, 256>>>(flag, cnt, cursor);                        // 1
    gemm_h_k<<<ggrid, 256, GEMM_SMEM>>>(xh, wt, b1, t1, nullptr, NNODES, FIN, 1);    // 2
    gemm_h_k<<<ggrid, 256, GEMM_SMEM>>>(t1, wt + WT2_OFF, b2, hh, nullptr,
                                        NNODES, HID, 0);                             // 3 <- ncu
    detect_k<<<16, 256>>>((const int*)ei, flag);                                     // 4
    convert_edges_k<<<(E + 255) / 256, 256>>>(ei, flag, src, dst, cnt, E);           // 5
    scanA_k<<<SCAN_B, 256>>>(cnt, bsum, dinv);
    scanB_k<<<SCAN_B, 256>>>(cnt, bsum, off);
    fill_k<<<(E + 255) / 256, 256>>>(src, dst, off, cursor, adj, E);

    // GCN layers
    int agg_blocks = (NNODES * 32 + 255) / 256;
    for (int l = 0; l < 3; l++) {
        gemm_h_k<<<ggrid, 256, GEMM_SMEM>>>(hh, wt + WTC_OFF + l * 65536, nullptr, gh,
                                            dinv, NNODES, HID, 0);
        aggregate_h_k<<<agg_blocks, 256>>>(off, adj, gh, dinv, convb + (size_t)l * HID, hh);
    }

    // pooling + heads + output
    pool_partial_k<<<PB, 256>>>(hh, psum, pmax);
    head_k<<<1, 512>>>(psum, pmax, Wg1, bg1, Wg2, bg2, Wd1, bd1, Wd2, bd2, (float*)d_out, prob);
    fill_probs_k<<<(E / 4 + 255) / 256, 256>>>((float*)d_out, prob, E);
}